// round 7
// baseline (speedup 1.0000x reference)
#include <cuda_runtime.h>
#include <cuda_bf16.h>
#include <math.h>
#include <stdint.h>

// ---------------------------------------------------------------------------
// Problem constants
// ---------------------------------------------------------------------------
#define DIMM   1024
#define INNER  512
#define BK_CH  256
#define NH     8
#define MQ     (BK_CH*64)       // 16384
#define MKV    (BK_CH*256)      // 65536

// ---------------------------------------------------------------------------
// Scratch
// ---------------------------------------------------------------------------
__device__ float g_Q[(size_t)MQ * INNER];
__device__ float g_K[(size_t)MKV * INNER];
__device__ float g_V[(size_t)MKV * INNER];
__device__ float g_O[(size_t)MQ * INNER];

// ---------------------------------------------------------------------------
// helpers
// ---------------------------------------------------------------------------
__device__ __forceinline__ unsigned f2tf(float f) {
    unsigned u; asm("cvt.rna.tf32.f32 %0, %1;" : "=r"(u) : "f"(f)); return u;
}
__device__ __forceinline__ void mma_tf32(float* c, const unsigned* a, const unsigned* b) {
    asm volatile(
        "mma.sync.aligned.m16n8k8.row.col.f32.tf32.tf32.f32 "
        "{%0,%1,%2,%3}, {%4,%5,%6,%7}, {%8,%9}, {%0,%1,%2,%3};\n"
        : "+f"(c[0]), "+f"(c[1]), "+f"(c[2]), "+f"(c[3])
        : "r"(a[0]), "r"(a[1]), "r"(a[2]), "r"(a[3]),
          "r"(b[0]), "r"(b[1]));
}
__device__ __forceinline__ void cpa16(uint32_t dst, const void* src, uint32_t ssize) {
    asm volatile("cp.async.cg.shared.global [%0], [%1], 16, %2;"
                 :: "r"(dst), "l"(src), "r"(ssize) : "memory");
}
__device__ __forceinline__ uint32_t smem_u32(const void* p) {
    uint32_t a;
    asm("{ .reg .u64 t; cvta.to.shared.u64 t, %1; cvt.u32.u64 %0, t; }" : "=r"(a) : "l"(p));
    return a;
}
#define CPA_COMMIT() asm volatile("cp.async.commit_group;" ::: "memory")
#define CPA_WAIT2()  asm volatile("cp.async.wait_group 2;" ::: "memory")

// k-slot permutation: mma k-slot s reads physical smem column 2*(s&3)+(s>>2)
// (applied identically to A and B, so the dot product is just reordered).
// => A slots (lk, lk+4) sit at adjacent physical columns (2lk, 2lk+1): float2 LDS.

// ---------------------------------------------------------------------------
// Fused K+V GEMM: Ck = A@Wk, Cv = A@Wv. BM=128,BN=128,BK=16, 4-stage cp.async.
// 256 threads, 8 warps (2x4), warp tile 64x32 per output matrix.
// ---------------------------------------------------------------------------
#define KV_STAGES 4
#define AS_STR  20
#define BS_STR  136
#define KV_A_F  (128*AS_STR)                  // 2560
#define KV_B_F  (16*BS_STR)                   // 2176
#define KV_STAGE_F (KV_A_F + 2*KV_B_F)        // 6912
#define KV_SMEM (KV_STAGES * KV_STAGE_F * 4)  // 110592 B

__global__ __launch_bounds__(256, 1)
void tf32_gemm_kv(const float* __restrict__ A,
                  const float* __restrict__ Wk, const float* __restrict__ Wv,
                  float* __restrict__ Ck, float* __restrict__ Cv,
                  int M, int N, int K)
{
    extern __shared__ float smf[];
    const uint32_t sbase = smem_u32(smf);

    const int n0 = blockIdx.x * 128;
    const int m0 = blockIdx.y * 128;
    const int t  = threadIdx.x;
    const int lane = t & 31;
    const int warp = t >> 5;
    const int m_base = (warp >> 2) * 64;
    const int n_base = (warp & 3) * 32;
    const int lg = lane >> 2;
    const int lk = lane & 3;
    const int kt = K / 16;

    const int arow  = t >> 1;
    const int acol0 = (t & 1) * 8;
    const float* Aptr = A + (size_t)(m0 + arow) * K;
    const int bkr   = t >> 4;
    const int bcol0 = (t & 15) * 8;
    const float* Kptr = Wk + (size_t)bkr * N + n0 + bcol0;
    const float* Vptr = Wv + (size_t)bkr * N + n0 + bcol0;

    auto load_stage = [&](int i) {
        const int buf = i % KV_STAGES;
        const int k0  = i * 16;
        const uint32_t sb = sbase + buf * (KV_STAGE_F * 4);
        cpa16(sb + (arow * AS_STR + acol0) * 4,     Aptr + k0 + acol0,     16);
        cpa16(sb + (arow * AS_STR + acol0 + 4) * 4, Aptr + k0 + acol0 + 4, 16);
        const uint32_t kb = sb + KV_A_F * 4;
        cpa16(kb + (bkr * BS_STR + bcol0) * 4,     Kptr + (size_t)k0 * N,     16);
        cpa16(kb + (bkr * BS_STR + bcol0 + 4) * 4, Kptr + (size_t)k0 * N + 4, 16);
        const uint32_t vb = kb + KV_B_F * 4;
        cpa16(vb + (bkr * BS_STR + bcol0) * 4,     Vptr + (size_t)k0 * N,     16);
        cpa16(vb + (bkr * BS_STR + bcol0 + 4) * 4, Vptr + (size_t)k0 * N + 4, 16);
    };

    float acck[4][4][4], accv[4][4][4];
    #pragma unroll
    for (int i = 0; i < 4; i++)
        #pragma unroll
        for (int j = 0; j < 4; j++)
            #pragma unroll
            for (int q = 0; q < 4; q++) { acck[i][j][q] = 0.f; accv[i][j][q] = 0.f; }

    #pragma unroll
    for (int s = 0; s < KV_STAGES - 1; s++) { load_stage(s); CPA_COMMIT(); }

    for (int i = 0; i < kt; i++) {
        CPA_WAIT2();
        __syncthreads();
        if (i + KV_STAGES - 1 < kt) load_stage(i + KV_STAGES - 1);
        CPA_COMMIT();

        const float* As = smf + (i % KV_STAGES) * KV_STAGE_F;
        const float* Bk = As + KV_A_F;
        const float* Bv = Bk + KV_B_F;

        #pragma unroll
        for (int kk0 = 0; kk0 < 16; kk0 += 8) {
            const int c0 = kk0 + 2 * lk;          // physical cols (c0, c0+1)
            unsigned afr[4][4];
            #pragma unroll
            for (int ii = 0; ii < 4; ii++) {
                const int mrow = m_base + ii * 16 + lg;
                float2 p = *(const float2*)&As[mrow * AS_STR + c0];
                float2 q = *(const float2*)&As[(mrow + 8) * AS_STR + c0];
                afr[ii][0] = f2tf(p.x); afr[ii][2] = f2tf(p.y);
                afr[ii][1] = f2tf(q.x); afr[ii][3] = f2tf(q.y);
            }
            unsigned bk[4][2], bv[4][2];
            #pragma unroll
            for (int j = 0; j < 4; j++) {
                const int ncol = n_base + j * 8 + lg;
                bk[j][0] = f2tf(Bk[c0 * BS_STR + ncol]);
                bk[j][1] = f2tf(Bk[(c0 + 1) * BS_STR + ncol]);
                bv[j][0] = f2tf(Bv[c0 * BS_STR + ncol]);
                bv[j][1] = f2tf(Bv[(c0 + 1) * BS_STR + ncol]);
            }
            #pragma unroll
            for (int ii = 0; ii < 4; ii++)
                #pragma unroll
                for (int j = 0; j < 4; j++) {
                    mma_tf32(acck[ii][j], afr[ii], bk[j]);
                    mma_tf32(accv[ii][j], afr[ii], bv[j]);
                }
        }
        __syncthreads();
    }

    #pragma unroll
    for (int i = 0; i < 4; i++) {
        const int r0 = m0 + m_base + i * 16 + lg;
        const int r1 = r0 + 8;
        #pragma unroll
        for (int j = 0; j < 4; j++) {
            const int col = n0 + n_base + j * 8 + (lk << 1);
            *(float2*)(Ck + (size_t)r0 * N + col) = make_float2(acck[i][j][0], acck[i][j][1]);
            *(float2*)(Ck + (size_t)r1 * N + col) = make_float2(acck[i][j][2], acck[i][j][3]);
            *(float2*)(Cv + (size_t)r0 * N + col) = make_float2(accv[i][j][0], accv[i][j][1]);
            *(float2*)(Cv + (size_t)r1 * N + col) = make_float2(accv[i][j][2], accv[i][j][3]);
        }
    }
}

// ---------------------------------------------------------------------------
// Single TF32 GEMM (Q and O projections), 4-stage cp.async + LDS.64 A.
// ---------------------------------------------------------------------------
#define SG_STAGES 4
#define SG_STAGE_F (128*AS_STR + 16*BS_STR)    // 4736
#define SG_SMEM (SG_STAGES * SG_STAGE_F * 4)   // 75776 B

template<int GATHER, int EPI>
__global__ __launch_bounds__(256, 2)
void tf32_gemm(const float* __restrict__ A, const float* __restrict__ W,
               float* __restrict__ C, int M, int N, int K,
               const float* __restrict__ bias)
{
    extern __shared__ float smf[];
    const uint32_t sbase = smem_u32(smf);

    const int n0 = blockIdx.x * 128;
    const int m0 = blockIdx.y * 128;
    const int t  = threadIdx.x;
    const int lane = t & 31;
    const int warp = t >> 5;
    const int m_base = (warp >> 2) * 64;
    const int n_base = (warp & 3) * 32;
    const int lg = lane >> 2;
    const int lk = lane & 3;
    const int kt = K / 16;

    const int arow  = t >> 1;
    const int acol0 = (t & 1) * 8;
    const float* Aptr; uint32_t asz = 16;
    {
        int gm = m0 + arow;
        if (GATHER == 1) {
            int pos = gm & 4095;
            if (pos < 4033) Aptr = A + (size_t)(gm + 63) * K;
            else { Aptr = A; asz = 0; }
        } else Aptr = A + (size_t)gm * K;
    }
    const int bkr   = t >> 4;
    const int bcol0 = (t & 15) * 8;
    const float* Wptr = W + (size_t)bkr * N + n0 + bcol0;

    auto load_stage = [&](int i) {
        const int buf = i % SG_STAGES;
        const int k0  = i * 16;
        const uint32_t sb = sbase + buf * (SG_STAGE_F * 4);
        cpa16(sb + (arow * AS_STR + acol0) * 4,     Aptr + k0 + acol0,     asz);
        cpa16(sb + (arow * AS_STR + acol0 + 4) * 4, Aptr + k0 + acol0 + 4, asz);
        const uint32_t bb = sb + 128 * AS_STR * 4;
        cpa16(bb + (bkr * BS_STR + bcol0) * 4,     Wptr + (size_t)k0 * N,     16);
        cpa16(bb + (bkr * BS_STR + bcol0 + 4) * 4, Wptr + (size_t)k0 * N + 4, 16);
    };

    float acc[4][4][4];
    #pragma unroll
    for (int i = 0; i < 4; i++)
        #pragma unroll
        for (int j = 0; j < 4; j++)
            #pragma unroll
            for (int q = 0; q < 4; q++) acc[i][j][q] = 0.f;

    #pragma unroll
    for (int s = 0; s < SG_STAGES - 1; s++) { load_stage(s); CPA_COMMIT(); }

    for (int i = 0; i < kt; i++) {
        CPA_WAIT2();
        __syncthreads();
        if (i + SG_STAGES - 1 < kt) load_stage(i + SG_STAGES - 1);
        CPA_COMMIT();

        const float* As = smf + (i % SG_STAGES) * SG_STAGE_F;
        const float* Bs = As + 128 * AS_STR;

        #pragma unroll
        for (int kk0 = 0; kk0 < 16; kk0 += 8) {
            const int c0 = kk0 + 2 * lk;
            unsigned afr[4][4], bfr[4][2];
            #pragma unroll
            for (int ii = 0; ii < 4; ii++) {
                const int mrow = m_base + ii * 16 + lg;
                float2 p = *(const float2*)&As[mrow * AS_STR + c0];
                float2 q = *(const float2*)&As[(mrow + 8) * AS_STR + c0];
                afr[ii][0] = f2tf(p.x); afr[ii][2] = f2tf(p.y);
                afr[ii][1] = f2tf(q.x); afr[ii][3] = f2tf(q.y);
            }
            #pragma unroll
            for (int j = 0; j < 4; j++) {
                const int ncol = n_base + j * 8 + lg;
                bfr[j][0] = f2tf(Bs[c0 * BS_STR + ncol]);
                bfr[j][1] = f2tf(Bs[(c0 + 1) * BS_STR + ncol]);
            }
            #pragma unroll
            for (int ii = 0; ii < 4; ii++)
                #pragma unroll
                for (int j = 0; j < 4; j++)
                    mma_tf32(acc[ii][j], afr[ii], bfr[j]);
        }
        __syncthreads();
    }

    #pragma unroll
    for (int i = 0; i < 4; i++) {
        const int r0 = m0 + m_base + i * 16 + lg;
        const int r1 = r0 + 8;
        #pragma unroll
        for (int j = 0; j < 4; j++) {
            const int col = n0 + n_base + j * 8 + (lk << 1);
            if (EPI == 0) {
                *(float2*)(C + (size_t)r0 * N + col) = make_float2(acc[i][j][0], acc[i][j][1]);
                *(float2*)(C + (size_t)r1 * N + col) = make_float2(acc[i][j][2], acc[i][j][3]);
            } else {
                const float2 bvv = *(const float2*)(bias + col);
                int pos0 = r0 & 4095;
                if (pos0 < 4033) {
                    const int bb = r0 >> 12;
                    float* p = C + ((size_t)bb * 4096 + pos0 + 63) * N + col;
                    *(float2*)p = make_float2(acc[i][j][0] + bvv.x, acc[i][j][1] + bvv.y);
                }
                int pos1 = r1 & 4095;
                if (pos1 < 4033) {
                    const int bb = r1 >> 12;
                    float* p = C + ((size_t)bb * 4096 + pos1 + 63) * N + col;
                    *(float2*)p = make_float2(acc[i][j][2] + bvv.x, acc[i][j][3] + bvv.y);
                }
            }
        }
    }
}

// ---------------------------------------------------------------------------
// Fused attention (unchanged from round 6)
// ---------------------------------------------------------------------------
#define SIMW 324
#define ATTN_SMEM ((32*68 + 64*68 + 32*SIMW) * 4)

__global__ __launch_bounds__(256)
void attn_kernel(const float* __restrict__ Q, const float* __restrict__ Kb,
                 const float* __restrict__ Vb,
                 const float* __restrict__ qpe63,
                 const float* __restrict__ kpe,
                 const float* __restrict__ null_k,
                 const float* __restrict__ null_v,
                 float* __restrict__ O)
{
    extern __shared__ float sm[];
    float* qs  = sm;                  // [32][68]
    float* kvs = qs + 32 * 68;        // [64][68]
    float* sim = kvs + 64 * 68;       // [32][SIMW]

    const int c    = blockIdx.x;
    const int h    = blockIdx.y;
    const int half = blockIdx.z;
    const int r0   = half * 32;
    const int t    = threadIdx.x;
    const int ty = t >> 4, tx = t & 15;
    const float scale = 0.125f;

    for (int e = t; e < 32 * 64; e += 256) {
        int i = e >> 6, d = e & 63;
        qs[i * 68 + d] = Q[((size_t)(c * 64 + r0 + i)) * INNER + h * 64 + d] * scale;
    }
    __syncthreads();

    if (half == 0) {
        float nq0 = 0.f;
        if (t < 64) {
            int d = t;
            float v = qs[d];
            float p = (d < 32) ? -qs[d + 32] : qs[d - 32];
            float f = qpe63[d];
            nq0 = v * cosf(f) + p * sinf(f);
        }
        __syncthreads();
        if (t < 64) qs[t] = nq0;
        __syncthreads();
    }

    for (int jt = 0; jt < 5; jt++) {
        for (int e = t; e < 64 * 64; e += 256) {
            int jj = e >> 6, d = e & 63;
            int j = jt * 64 + jj;
            float val = 0.f;
            if (j == 0)       val = null_k[h * 64 + d];
            else if (j < 257) val = Kb[((size_t)(c * 256 + j - 1)) * INNER + h * 64 + d];
            kvs[jj * 68 + d] = val;
        }
        __syncthreads();
        float nv[16];
        {
            int q = 0;
            for (int e = t; e < 64 * 64; e += 256, q++) {
                int jj = e >> 6, d = e & 63;
                int j = jt * 64 + jj;
                float val = kvs[jj * 68 + d];
                if (j >= 1 && j < 257) {
                    int kr = (j - 1) & 127;
                    float f = kpe[kr * 64 + d];
                    float p = (d < 32) ? -kvs[jj * 68 + d + 32] : kvs[jj * 68 + d - 32];
                    val = val * cosf(f) + p * sinf(f);
                }
                nv[q] = val;
            }
        }
        __syncthreads();
        {
            int q = 0;
            for (int e = t; e < 64 * 64; e += 256, q++) {
                int jj = e >> 6, d = e & 63;
                kvs[jj * 68 + d] = nv[q];
            }
        }
        __syncthreads();

        float s[2][4];
        #pragma unroll
        for (int i = 0; i < 2; i++)
            #pragma unroll
            for (int j = 0; j < 4; j++) s[i][j] = 0.f;
        for (int d = 0; d < 64; d++) {
            float a[2], b[4];
            #pragma unroll
            for (int i = 0; i < 2; i++) a[i] = qs[(ty * 2 + i) * 68 + d];
            #pragma unroll
            for (int j = 0; j < 4; j++) b[j] = kvs[(tx * 4 + j) * 68 + d];
            #pragma unroll
            for (int i = 0; i < 2; i++)
                #pragma unroll
                for (int j = 0; j < 4; j++) s[i][j] = fmaf(a[i], b[j], s[i][j]);
        }
        #pragma unroll
        for (int i = 0; i < 2; i++)
            #pragma unroll
            for (int j = 0; j < 4; j++)
                sim[(ty * 2 + i) * SIMW + jt * 64 + tx * 4 + j] = s[i][j];
        __syncthreads();
    }

    {
        const int warp = t >> 5, lanei = t & 31;
        for (int i = warp; i < 32; i += 8) {
            float* row = sim + i * SIMW;
            float mx = -1e30f;
            for (int j = lanei; j < 257; j += 32) mx = fmaxf(mx, row[j]);
            #pragma unroll
            for (int o = 16; o; o >>= 1) mx = fmaxf(mx, __shfl_xor_sync(~0u, mx, o));
            float sum = 0.f;
            for (int j = lanei; j < 257; j += 32) {
                float e = __expf(row[j] - mx);
                row[j] = e;
                sum += e;
            }
            #pragma unroll
            for (int o = 16; o; o >>= 1) sum += __shfl_xor_sync(~0u, sum, o);
            float inv = 1.f / sum;
            for (int j = lanei; j < 257; j += 32) row[j] *= inv;
        }
    }
    __syncthreads();

    float oacc[2][4];
    #pragma unroll
    for (int i = 0; i < 2; i++)
        #pragma unroll
        for (int j = 0; j < 4; j++) oacc[i][j] = 0.f;

    for (int jt = 0; jt < 5; jt++) {
        for (int e = t; e < 64 * 64; e += 256) {
            int jj = e >> 6, d = e & 63;
            int j = jt * 64 + jj;
            float val = 0.f;
            if (j == 0)       val = null_v[h * 64 + d];
            else if (j < 257) val = Vb[((size_t)(c * 256 + j - 1)) * INNER + h * 64 + d];
            kvs[jj * 68 + d] = val;
        }
        __syncthreads();

        const int jmax = (jt == 4) ? 1 : 64;
        for (int jj = 0; jj < jmax; jj++) {
            int j = jt * 64 + jj;
            float a[2], b[4];
            #pragma unroll
            for (int i = 0; i < 2; i++) a[i] = sim[(ty * 2 + i) * SIMW + j];
            #pragma unroll
            for (int d = 0; d < 4; d++) b[d] = kvs[jj * 68 + tx * 4 + d];
            #pragma unroll
            for (int i = 0; i < 2; i++)
                #pragma unroll
                for (int d = 0; d < 4; d++)
                    oacc[i][d] = fmaf(a[i], b[d], oacc[i][d]);
        }
        __syncthreads();
    }

    #pragma unroll
    for (int i = 0; i < 2; i++)
        #pragma unroll
        for (int d = 0; d < 4; d++)
            O[((size_t)(c * 64 + r0 + ty * 2 + i)) * INNER + h * 64 + tx * 4 + d] = oacc[i][d];
}

// ---------------------------------------------------------------------------
// Zero the first 63 token rows of each batch
// ---------------------------------------------------------------------------
__global__ void zero_prefix_kernel(float* __restrict__ out)
{
    size_t idx = (size_t)blockIdx.x * 256 + threadIdx.x;
    const size_t total = (size_t)4 * 63 * 1024;
    if (idx < total) {
        size_t b   = idx / (63 * 1024);
        size_t rem = idx % (63 * 1024);
        out[b * (size_t)4096 * 1024 + rem] = 0.f;
    }
}

// ---------------------------------------------------------------------------
// Launch
// ---------------------------------------------------------------------------
extern "C" void kernel_launch(void* const* d_in, const int* in_sizes, int n_in,
                              void* d_out, int out_size)
{
    const float* x        = (const float*)d_in[0];
    const float* context  = (const float*)d_in[1];
    const float* q_pos    = (const float*)d_in[2];
    const float* k_pos    = (const float*)d_in[3];
    const float* Wq       = (const float*)d_in[4];
    const float* Wk       = (const float*)d_in[5];
    const float* Wv       = (const float*)d_in[6];
    const float* Wo       = (const float*)d_in[7];
    const float* bo       = (const float*)d_in[8];
    const float* null_k   = (const float*)d_in[9];
    const float* null_v   = (const float*)d_in[10];
    float* out            = (float*)d_out;

    float *Qb, *Kb, *Vb, *Ob;
    cudaGetSymbolAddress((void**)&Qb, g_Q);
    cudaGetSymbolAddress((void**)&Kb, g_K);
    cudaGetSymbolAddress((void**)&Vb, g_V);
    cudaGetSymbolAddress((void**)&Ob, g_O);

    cudaFuncSetAttribute(tf32_gemm<1,0>, cudaFuncAttributeMaxDynamicSharedMemorySize, SG_SMEM);
    cudaFuncSetAttribute(tf32_gemm<0,1>, cudaFuncAttributeMaxDynamicSharedMemorySize, SG_SMEM);
    cudaFuncSetAttribute(tf32_gemm_kv,   cudaFuncAttributeMaxDynamicSharedMemorySize, KV_SMEM);
    cudaFuncSetAttribute(attn_kernel,    cudaFuncAttributeMaxDynamicSharedMemorySize, ATTN_SMEM);

    // Q = shifted-x @ Wq
    {
        dim3 grid(INNER / 128, MQ / 128);
        tf32_gemm<1, 0><<<grid, 256, SG_SMEM>>>(x, Wq, Qb, MQ, INNER, DIMM, nullptr);
    }
    // K,V = context @ {Wk,Wv} (fused, shared A tiles)
    {
        dim3 grid(INNER / 128, MKV / 128);
        tf32_gemm_kv<<<grid, 256, KV_SMEM>>>(context, Wk, Wv, Kb, Vb, MKV, INNER, DIMM);
    }
    // fused rope + attention
    {
        dim3 grid(BK_CH, NH, 2);
        attn_kernel<<<grid, 256, ATTN_SMEM>>>(Qb, Kb, Vb,
                                              q_pos + 63 * 64, k_pos,
                                              null_k, null_v, Ob);
    }
    // out = attn_out @ Wo + bo, scattered with +63 shift
    {
        dim3 grid(DIMM / 128, MQ / 128);
        tf32_gemm<0, 1><<<grid, 256, SG_SMEM>>>(Ob, Wo, out, MQ, DIMM, INNER, bo);
    }
    // zero first 63 rows per batch
    {
        const int total = 4 * 63 * 1024;
        zero_prefix_kernel<<<(total + 255) / 256, 256>>>(out);
    }
}

// round 8
// speedup vs baseline: 1.4884x; 1.4884x over previous
#include <cuda_runtime.h>
#include <cuda_bf16.h>
#include <math.h>
#include <stdint.h>

// ---------------------------------------------------------------------------
// Problem constants
// ---------------------------------------------------------------------------
#define DIMM   1024
#define INNER  512
#define BK_CH  256
#define NH     8
#define MQ     (BK_CH*64)       // 16384
#define MKV    (BK_CH*256)      // 65536
#define NX     (4*4096)         // x rows

// ---------------------------------------------------------------------------
// Scratch
// ---------------------------------------------------------------------------
__device__ float    g_Q[(size_t)MQ * INNER];
__device__ float    g_K[(size_t)MKV * INNER];
__device__ float    g_V[(size_t)MKV * INNER];
__device__ unsigned g_O[(size_t)MQ * INNER];          // tf32 bits (attn writes)
__device__ unsigned g_xtf[(size_t)NX * DIMM];         // tf32 x
__device__ unsigned g_ctf[(size_t)MKV * DIMM];        // tf32 context
__device__ unsigned g_wq[(size_t)DIMM * INNER];
__device__ unsigned g_wk[(size_t)DIMM * INNER];
__device__ unsigned g_wv[(size_t)DIMM * INNER];
__device__ unsigned g_wo[(size_t)INNER * DIMM];

// ---------------------------------------------------------------------------
// helpers
// ---------------------------------------------------------------------------
__device__ __forceinline__ unsigned f2tf(float f) {
    unsigned u; asm("cvt.rna.tf32.f32 %0, %1;" : "=r"(u) : "f"(f)); return u;
}
__device__ __forceinline__ void mma_tf32(float* c, const unsigned* a, const unsigned* b) {
    asm volatile(
        "mma.sync.aligned.m16n8k8.row.col.f32.tf32.tf32.f32 "
        "{%0,%1,%2,%3}, {%4,%5,%6,%7}, {%8,%9}, {%0,%1,%2,%3};\n"
        : "+f"(c[0]), "+f"(c[1]), "+f"(c[2]), "+f"(c[3])
        : "r"(a[0]), "r"(a[1]), "r"(a[2]), "r"(a[3]),
          "r"(b[0]), "r"(b[1]));
}
__device__ __forceinline__ void cpa16(uint32_t dst, const void* src, uint32_t ssize) {
    asm volatile("cp.async.cg.shared.global [%0], [%1], 16, %2;"
                 :: "r"(dst), "l"(src), "r"(ssize) : "memory");
}
__device__ __forceinline__ uint32_t smem_u32(const void* p) {
    uint32_t a;
    asm("{ .reg .u64 t; cvta.to.shared.u64 t, %1; cvt.u32.u64 %0, t; }" : "=r"(a) : "l"(p));
    return a;
}
#define CPA_COMMIT() asm volatile("cp.async.commit_group;" ::: "memory")
#define CPA_WAIT2()  asm volatile("cp.async.wait_group 2;" ::: "memory")

// ---------------------------------------------------------------------------
// Elementwise fp32 -> tf32-bits conversion (vectorized)
// ---------------------------------------------------------------------------
__global__ void cvt_tf32_kernel(const float4* __restrict__ in,
                                uint4* __restrict__ out, int n4)
{
    int i = blockIdx.x * blockDim.x + threadIdx.x;
    if (i < n4) {
        float4 v = in[i];
        out[i] = make_uint4(f2tf(v.x), f2tf(v.y), f2tf(v.z), f2tf(v.w));
    }
}

// ---------------------------------------------------------------------------
// TF32 GEMM, pre-converted operands: C[M,N] = A[M,K] @ W[K,N]
// BM=128,BN=128,BK=16; 4-stage cp.async; 256 threads (8 warps 2x4),
// warp tile 64x32. k-slot permutation s -> 2(s&3)+(s>>2) gives LDS.64 A.
// ---------------------------------------------------------------------------
#define SG_STAGES 4
#define AS_STR  20
#define BS_STR  136
#define SG_STAGE_F (128*AS_STR + 16*BS_STR)    // 4736
#define SG_SMEM (SG_STAGES * SG_STAGE_F * 4)   // 75776 B

template<int GATHER, int EPI>
__global__ __launch_bounds__(256, 2)
void tf32_gemm(const unsigned* __restrict__ A, const unsigned* __restrict__ W,
               float* __restrict__ C, int M, int N, int K,
               const float* __restrict__ bias)
{
    extern __shared__ unsigned smu[];
    const uint32_t sbase = smem_u32(smu);

    const int n0 = blockIdx.x * 128;
    const int m0 = blockIdx.y * 128;
    const int t  = threadIdx.x;
    const int lane = t & 31;
    const int warp = t >> 5;
    const int m_base = (warp >> 2) * 64;
    const int n_base = (warp & 3) * 32;
    const int lg = lane >> 2;
    const int lk = lane & 3;
    const int kt = K / 16;

    const int arow  = t >> 1;
    const int acol0 = (t & 1) * 8;
    const unsigned* Aptr; uint32_t asz = 16;
    {
        int gm = m0 + arow;
        if (GATHER == 1) {
            int pos = gm & 4095;
            if (pos < 4033) Aptr = A + (size_t)(gm + 63) * K;
            else { Aptr = A; asz = 0; }
        } else Aptr = A + (size_t)gm * K;
    }
    const int bkr   = t >> 4;
    const int bcol0 = (t & 15) * 8;
    const unsigned* Wptr = W + (size_t)bkr * N + n0 + bcol0;

    auto load_stage = [&](int i) {
        const int buf = i % SG_STAGES;
        const int k0  = i * 16;
        const uint32_t sb = sbase + buf * (SG_STAGE_F * 4);
        cpa16(sb + (arow * AS_STR + acol0) * 4,     Aptr + k0 + acol0,     asz);
        cpa16(sb + (arow * AS_STR + acol0 + 4) * 4, Aptr + k0 + acol0 + 4, asz);
        const uint32_t bb = sb + 128 * AS_STR * 4;
        cpa16(bb + (bkr * BS_STR + bcol0) * 4,     Wptr + (size_t)k0 * N,     16);
        cpa16(bb + (bkr * BS_STR + bcol0 + 4) * 4, Wptr + (size_t)k0 * N + 4, 16);
    };

    float acc[4][4][4];
    #pragma unroll
    for (int i = 0; i < 4; i++)
        #pragma unroll
        for (int j = 0; j < 4; j++)
            #pragma unroll
            for (int q = 0; q < 4; q++) acc[i][j][q] = 0.f;

    #pragma unroll
    for (int s = 0; s < SG_STAGES - 1; s++) { load_stage(s); CPA_COMMIT(); }

    for (int i = 0; i < kt; i++) {
        CPA_WAIT2();
        __syncthreads();
        if (i + SG_STAGES - 1 < kt) load_stage(i + SG_STAGES - 1);
        CPA_COMMIT();

        const unsigned* As = smu + (size_t)(i % SG_STAGES) * SG_STAGE_F;
        const unsigned* Bs = As + 128 * AS_STR;

        #pragma unroll
        for (int kk0 = 0; kk0 < 16; kk0 += 8) {
            const int c0 = kk0 + 2 * lk;          // physical cols (c0, c0+1)
            unsigned afr[4][4], bfr[4][2];
            #pragma unroll
            for (int ii = 0; ii < 4; ii++) {
                const int mrow = m_base + ii * 16 + lg;
                uint2 p = *(const uint2*)&As[mrow * AS_STR + c0];
                uint2 q = *(const uint2*)&As[(mrow + 8) * AS_STR + c0];
                afr[ii][0] = p.x; afr[ii][2] = p.y;
                afr[ii][1] = q.x; afr[ii][3] = q.y;
            }
            #pragma unroll
            for (int j = 0; j < 4; j++) {
                const int ncol = n_base + j * 8 + lg;
                bfr[j][0] = Bs[c0 * BS_STR + ncol];
                bfr[j][1] = Bs[(c0 + 1) * BS_STR + ncol];
            }
            #pragma unroll
            for (int ii = 0; ii < 4; ii++)
                #pragma unroll
                for (int j = 0; j < 4; j++)
                    mma_tf32(acc[ii][j], afr[ii], bfr[j]);
        }
        __syncthreads();
    }

    #pragma unroll
    for (int i = 0; i < 4; i++) {
        const int r0 = m0 + m_base + i * 16 + lg;
        const int r1 = r0 + 8;
        #pragma unroll
        for (int j = 0; j < 4; j++) {
            const int col = n0 + n_base + j * 8 + (lk << 1);
            if (EPI == 0) {
                *(float2*)(C + (size_t)r0 * N + col) = make_float2(acc[i][j][0], acc[i][j][1]);
                *(float2*)(C + (size_t)r1 * N + col) = make_float2(acc[i][j][2], acc[i][j][3]);
            } else {
                const float2 bvv = *(const float2*)(bias + col);
                int pos0 = r0 & 4095;
                if (pos0 < 4033) {
                    const int bb = r0 >> 12;
                    float* p = C + ((size_t)bb * 4096 + pos0 + 63) * N + col;
                    *(float2*)p = make_float2(acc[i][j][0] + bvv.x, acc[i][j][1] + bvv.y);
                }
                int pos1 = r1 & 4095;
                if (pos1 < 4033) {
                    const int bb = r1 >> 12;
                    float* p = C + ((size_t)bb * 4096 + pos1 + 63) * N + col;
                    *(float2*)p = make_float2(acc[i][j][2] + bvv.x, acc[i][j][3] + bvv.y);
                }
            }
        }
    }
}

// ---------------------------------------------------------------------------
// Fused attention (round-6 structure; output stored as tf32 bits)
// ---------------------------------------------------------------------------
#define SIMW 324
#define ATTN_SMEM ((32*68 + 64*68 + 32*SIMW) * 4)

__global__ __launch_bounds__(256)
void attn_kernel(const float* __restrict__ Q, const float* __restrict__ Kb,
                 const float* __restrict__ Vb,
                 const float* __restrict__ qpe63,
                 const float* __restrict__ kpe,
                 const float* __restrict__ null_k,
                 const float* __restrict__ null_v,
                 unsigned* __restrict__ O)
{
    extern __shared__ float sm[];
    float* qs  = sm;                  // [32][68]
    float* kvs = qs + 32 * 68;        // [64][68]
    float* sim = kvs + 64 * 68;       // [32][SIMW]

    const int c    = blockIdx.x;
    const int h    = blockIdx.y;
    const int half = blockIdx.z;
    const int r0   = half * 32;
    const int t    = threadIdx.x;
    const int ty = t >> 4, tx = t & 15;
    const float scale = 0.125f;

    for (int e = t; e < 32 * 64; e += 256) {
        int i = e >> 6, d = e & 63;
        qs[i * 68 + d] = Q[((size_t)(c * 64 + r0 + i)) * INNER + h * 64 + d] * scale;
    }
    __syncthreads();

    if (half == 0) {
        float nq0 = 0.f;
        if (t < 64) {
            int d = t;
            float v = qs[d];
            float p = (d < 32) ? -qs[d + 32] : qs[d - 32];
            float f = qpe63[d];
            nq0 = v * cosf(f) + p * sinf(f);
        }
        __syncthreads();
        if (t < 64) qs[t] = nq0;
        __syncthreads();
    }

    for (int jt = 0; jt < 5; jt++) {
        for (int e = t; e < 64 * 64; e += 256) {
            int jj = e >> 6, d = e & 63;
            int j = jt * 64 + jj;
            float val = 0.f;
            if (j == 0)       val = null_k[h * 64 + d];
            else if (j < 257) val = Kb[((size_t)(c * 256 + j - 1)) * INNER + h * 64 + d];
            kvs[jj * 68 + d] = val;
        }
        __syncthreads();
        float nv[16];
        {
            int q = 0;
            for (int e = t; e < 64 * 64; e += 256, q++) {
                int jj = e >> 6, d = e & 63;
                int j = jt * 64 + jj;
                float val = kvs[jj * 68 + d];
                if (j >= 1 && j < 257) {
                    int kr = (j - 1) & 127;
                    float f = kpe[kr * 64 + d];
                    float p = (d < 32) ? -kvs[jj * 68 + d + 32] : kvs[jj * 68 + d - 32];
                    val = val * cosf(f) + p * sinf(f);
                }
                nv[q] = val;
            }
        }
        __syncthreads();
        {
            int q = 0;
            for (int e = t; e < 64 * 64; e += 256, q++) {
                int jj = e >> 6, d = e & 63;
                kvs[jj * 68 + d] = nv[q];
            }
        }
        __syncthreads();

        float s[2][4];
        #pragma unroll
        for (int i = 0; i < 2; i++)
            #pragma unroll
            for (int j = 0; j < 4; j++) s[i][j] = 0.f;
        for (int d = 0; d < 64; d++) {
            float a[2], b[4];
            #pragma unroll
            for (int i = 0; i < 2; i++) a[i] = qs[(ty * 2 + i) * 68 + d];
            #pragma unroll
            for (int j = 0; j < 4; j++) b[j] = kvs[(tx * 4 + j) * 68 + d];
            #pragma unroll
            for (int i = 0; i < 2; i++)
                #pragma unroll
                for (int j = 0; j < 4; j++) s[i][j] = fmaf(a[i], b[j], s[i][j]);
        }
        #pragma unroll
        for (int i = 0; i < 2; i++)
            #pragma unroll
            for (int j = 0; j < 4; j++)
                sim[(ty * 2 + i) * SIMW + jt * 64 + tx * 4 + j] = s[i][j];
        __syncthreads();
    }

    {
        const int warp = t >> 5, lanei = t & 31;
        for (int i = warp; i < 32; i += 8) {
            float* row = sim + i * SIMW;
            float mx = -1e30f;
            for (int j = lanei; j < 257; j += 32) mx = fmaxf(mx, row[j]);
            #pragma unroll
            for (int o = 16; o; o >>= 1) mx = fmaxf(mx, __shfl_xor_sync(~0u, mx, o));
            float sum = 0.f;
            for (int j = lanei; j < 257; j += 32) {
                float e = __expf(row[j] - mx);
                row[j] = e;
                sum += e;
            }
            #pragma unroll
            for (int o = 16; o; o >>= 1) sum += __shfl_xor_sync(~0u, sum, o);
            float inv = 1.f / sum;
            for (int j = lanei; j < 257; j += 32) row[j] *= inv;
        }
    }
    __syncthreads();

    float oacc[2][4];
    #pragma unroll
    for (int i = 0; i < 2; i++)
        #pragma unroll
        for (int j = 0; j < 4; j++) oacc[i][j] = 0.f;

    for (int jt = 0; jt < 5; jt++) {
        for (int e = t; e < 64 * 64; e += 256) {
            int jj = e >> 6, d = e & 63;
            int j = jt * 64 + jj;
            float val = 0.f;
            if (j == 0)       val = null_v[h * 64 + d];
            else if (j < 257) val = Vb[((size_t)(c * 256 + j - 1)) * INNER + h * 64 + d];
            kvs[jj * 68 + d] = val;
        }
        __syncthreads();

        const int jmax = (jt == 4) ? 1 : 64;
        for (int jj = 0; jj < jmax; jj++) {
            int j = jt * 64 + jj;
            float a[2], b[4];
            #pragma unroll
            for (int i = 0; i < 2; i++) a[i] = sim[(ty * 2 + i) * SIMW + j];
            #pragma unroll
            for (int d = 0; d < 4; d++) b[d] = kvs[jj * 68 + tx * 4 + d];
            #pragma unroll
            for (int i = 0; i < 2; i++)
                #pragma unroll
                for (int d = 0; d < 4; d++)
                    oacc[i][d] = fmaf(a[i], b[d], oacc[i][d]);
        }
        __syncthreads();
    }

    #pragma unroll
    for (int i = 0; i < 2; i++)
        #pragma unroll
        for (int d = 0; d < 4; d++)
            O[((size_t)(c * 64 + r0 + ty * 2 + i)) * INNER + h * 64 + tx * 4 + d]
                = f2tf(oacc[i][d]);
}

// ---------------------------------------------------------------------------
// Zero the first 63 token rows of each batch
// ---------------------------------------------------------------------------
__global__ void zero_prefix_kernel(float* __restrict__ out)
{
    size_t idx = (size_t)blockIdx.x * 256 + threadIdx.x;
    const size_t total = (size_t)4 * 63 * 1024;
    if (idx < total) {
        size_t b   = idx / (63 * 1024);
        size_t rem = idx % (63 * 1024);
        out[b * (size_t)4096 * 1024 + rem] = 0.f;
    }
}

// ---------------------------------------------------------------------------
// Launch
// ---------------------------------------------------------------------------
static void cvt_launch(const float* src, unsigned* dst, size_t n) {
    int n4 = (int)(n / 4);
    cvt_tf32_kernel<<<(n4 + 255) / 256, 256>>>((const float4*)src, (uint4*)dst, n4);
}

extern "C" void kernel_launch(void* const* d_in, const int* in_sizes, int n_in,
                              void* d_out, int out_size)
{
    const float* x        = (const float*)d_in[0];
    const float* context  = (const float*)d_in[1];
    const float* q_pos    = (const float*)d_in[2];
    const float* k_pos    = (const float*)d_in[3];
    const float* Wq       = (const float*)d_in[4];
    const float* Wk       = (const float*)d_in[5];
    const float* Wv       = (const float*)d_in[6];
    const float* Wo       = (const float*)d_in[7];
    const float* bo       = (const float*)d_in[8];
    const float* null_k   = (const float*)d_in[9];
    const float* null_v   = (const float*)d_in[10];
    float* out            = (float*)d_out;

    float *Qb, *Kb, *Vb;
    unsigned *Ob, *Xtf, *Ctf, *Wqf, *Wkf, *Wvf, *Wof;
    cudaGetSymbolAddress((void**)&Qb,  g_Q);
    cudaGetSymbolAddress((void**)&Kb,  g_K);
    cudaGetSymbolAddress((void**)&Vb,  g_V);
    cudaGetSymbolAddress((void**)&Ob,  g_O);
    cudaGetSymbolAddress((void**)&Xtf, g_xtf);
    cudaGetSymbolAddress((void**)&Ctf, g_ctf);
    cudaGetSymbolAddress((void**)&Wqf, g_wq);
    cudaGetSymbolAddress((void**)&Wkf, g_wk);
    cudaGetSymbolAddress((void**)&Wvf, g_wv);
    cudaGetSymbolAddress((void**)&Wof, g_wo);

    cudaFuncSetAttribute(tf32_gemm<1,0>, cudaFuncAttributeMaxDynamicSharedMemorySize, SG_SMEM);
    cudaFuncSetAttribute(tf32_gemm<0,0>, cudaFuncAttributeMaxDynamicSharedMemorySize, SG_SMEM);
    cudaFuncSetAttribute(tf32_gemm<0,1>, cudaFuncAttributeMaxDynamicSharedMemorySize, SG_SMEM);
    cudaFuncSetAttribute(attn_kernel,    cudaFuncAttributeMaxDynamicSharedMemorySize, ATTN_SMEM);

    // pre-convert all GEMM operands to tf32 bits
    cvt_launch(x,       Xtf, (size_t)NX * DIMM);
    cvt_launch(context, Ctf, (size_t)MKV * DIMM);
    cvt_launch(Wq,      Wqf, (size_t)DIMM * INNER);
    cvt_launch(Wk,      Wkf, (size_t)DIMM * INNER);
    cvt_launch(Wv,      Wvf, (size_t)DIMM * INNER);
    cvt_launch(Wo,      Wof, (size_t)INNER * DIMM);

    // Q = shifted-x @ Wq
    {
        dim3 grid(INNER / 128, MQ / 128);
        tf32_gemm<1, 0><<<grid, 256, SG_SMEM>>>(Xtf, Wqf, Qb, MQ, INNER, DIMM, nullptr);
    }
    // K = context @ Wk ; V = context @ Wv
    {
        dim3 grid(INNER / 128, MKV / 128);
        tf32_gemm<0, 0><<<grid, 256, SG_SMEM>>>(Ctf, Wkf, Kb, MKV, INNER, DIMM, nullptr);
        tf32_gemm<0, 0><<<grid, 256, SG_SMEM>>>(Ctf, Wvf, Vb, MKV, INNER, DIMM, nullptr);
    }
    // fused rope + attention (writes tf32 bits)
    {
        dim3 grid(BK_CH, NH, 2);
        attn_kernel<<<grid, 256, ATTN_SMEM>>>(Qb, Kb, Vb,
                                              q_pos + 63 * 64, k_pos,
                                              null_k, null_v, Ob);
    }
    // out = attn_out @ Wo + bo, scattered with +63 shift
    {
        dim3 grid(DIMM / 128, MQ / 128);
        tf32_gemm<0, 1><<<grid, 256, SG_SMEM>>>(Ob, Wof, out, MQ, DIMM, INNER, bo);
    }
    // zero first 63 rows per batch
    {
        const int total = 4 * 63 * 1024;
        zero_prefix_kernel<<<(total + 255) / 256, 256>>>(out);
    }
}

// round 9
// speedup vs baseline: 2.2410x; 1.5056x over previous
#include <cuda_runtime.h>
#include <cuda_fp16.h>
#include <math.h>
#include <stdint.h>

// ---------------------------------------------------------------------------
// Problem constants
// ---------------------------------------------------------------------------
#define DIMM   1024
#define INNER  512
#define BK_CH  256
#define NH     8
#define MQ     (BK_CH*64)       // 16384
#define MKV    (BK_CH*256)      // 65536
#define NX     (4*4096)

// ---------------------------------------------------------------------------
// Scratch
// ---------------------------------------------------------------------------
__device__ float  g_Q[(size_t)MQ * INNER];
__device__ float  g_K[(size_t)MKV * INNER];
__device__ float  g_V[(size_t)MKV * INNER];
__device__ __half g_O[(size_t)MQ * INNER];          // attn output (fp16)
__device__ __half g_xh[(size_t)NX * DIMM];
__device__ __half g_ch[(size_t)MKV * DIMM];
__device__ __half g_wq[(size_t)DIMM * INNER];
__device__ __half g_wk[(size_t)DIMM * INNER];
__device__ __half g_wv[(size_t)DIMM * INNER];
__device__ __half g_wo[(size_t)INNER * DIMM];

// ---------------------------------------------------------------------------
// helpers
// ---------------------------------------------------------------------------
__device__ __forceinline__ uint32_t smem_u32(const void* p) {
    uint32_t a;
    asm("{ .reg .u64 t; cvta.to.shared.u64 t, %1; cvt.u32.u64 %0, t; }" : "=r"(a) : "l"(p));
    return a;
}
__device__ __forceinline__ void mma_f16(float* c, const unsigned* a, const unsigned* b) {
    asm volatile(
        "mma.sync.aligned.m16n8k16.row.col.f32.f16.f16.f32 "
        "{%0,%1,%2,%3}, {%4,%5,%6,%7}, {%8,%9}, {%0,%1,%2,%3};\n"
        : "+f"(c[0]), "+f"(c[1]), "+f"(c[2]), "+f"(c[3])
        : "r"(a[0]), "r"(a[1]), "r"(a[2]), "r"(a[3]),
          "r"(b[0]), "r"(b[1]));
}
__device__ __forceinline__ void ldsm_x4(unsigned& r0, unsigned& r1,
                                        unsigned& r2, unsigned& r3, uint32_t a) {
    asm volatile("ldmatrix.sync.aligned.m8n8.x4.shared.b16 {%0,%1,%2,%3}, [%4];"
                 : "=r"(r0), "=r"(r1), "=r"(r2), "=r"(r3) : "r"(a));
}
__device__ __forceinline__ void ldsm_x4t(unsigned& r0, unsigned& r1,
                                         unsigned& r2, unsigned& r3, uint32_t a) {
    asm volatile("ldmatrix.sync.aligned.m8n8.x4.trans.shared.b16 {%0,%1,%2,%3}, [%4];"
                 : "=r"(r0), "=r"(r1), "=r"(r2), "=r"(r3) : "r"(a));
}
__device__ __forceinline__ void cpa16(uint32_t dst, const void* src, uint32_t ssize) {
    asm volatile("cp.async.cg.shared.global [%0], [%1], 16, %2;"
                 :: "r"(dst), "l"(src), "r"(ssize) : "memory");
}
#define CPA_COMMIT() asm volatile("cp.async.commit_group;" ::: "memory")
#define CPA_WAIT2()  asm volatile("cp.async.wait_group 2;" ::: "memory")

// ---------------------------------------------------------------------------
// Dual fp32 -> fp16 conversion (2 tensors per launch), float4 -> 4 halves
// ---------------------------------------------------------------------------
__global__ void cvt_f16_dual(const float4* __restrict__ in1, uint2* __restrict__ out1, int n1,
                             const float4* __restrict__ in2, uint2* __restrict__ out2, int n2)
{
    int i = blockIdx.x * blockDim.x + threadIdx.x;
    if (i < n1) {
        float4 v = in1[i];
        __half2 a = __floats2half2_rn(v.x, v.y);
        __half2 b = __floats2half2_rn(v.z, v.w);
        out1[i] = make_uint2(*(unsigned*)&a, *(unsigned*)&b);
    } else if (i - n1 < n2) {
        int j = i - n1;
        float4 v = in2[j];
        __half2 a = __floats2half2_rn(v.x, v.y);
        __half2 b = __floats2half2_rn(v.z, v.w);
        out2[j] = make_uint2(*(unsigned*)&a, *(unsigned*)&b);
    }
}

// ---------------------------------------------------------------------------
// FP16 GEMM: C[M,N] = A[M,K] @ W[K,N], fp32 accumulate.
// BM=128, BN=128, BK=32; 4-stage cp.async; 256 threads (8 warps 2x4),
// warp tile 64x32 (m16n8k16). ldmatrix for both fragments.
// A smem [m][k] stride 40 halves (80B); B smem [k][n] stride 136 halves (272B).
// ---------------------------------------------------------------------------
#define FG_STAGES 4
#define A_STR_H  40
#define B_STR_H  136
#define A_STAGE_B (128 * A_STR_H * 2)           // 10240
#define B_STAGE_B (32 * B_STR_H * 2)            // 8704
#define STAGE_B   (A_STAGE_B + B_STAGE_B)       // 18944
#define FG_SMEM   (FG_STAGES * STAGE_B)         // 75776

template<int GATHER, int EPI>
__global__ __launch_bounds__(256, 2)
void f16_gemm(const __half* __restrict__ A, const __half* __restrict__ W,
              float* __restrict__ C, int M, int N, int K,
              const float* __restrict__ bias)
{
    extern __shared__ char smc[];
    const uint32_t sbase = smem_u32(smc);

    const int n0 = blockIdx.x * 128;
    const int m0 = blockIdx.y * 128;
    const int t  = threadIdx.x;
    const int lane = t & 31;
    const int warp = t >> 5;
    const int m_base = (warp >> 2) * 64;
    const int n_base = (warp & 3) * 32;
    const int lg = lane >> 2;
    const int lk = lane & 3;
    const int kt = K / 32;

    // A loader: row = t>>1, byte-offset (t&1)*32 within the 64B row
    const int arow = t >> 1;
    const int aoff = (t & 1) * 16;               // halves
    const __half* Aptr; uint32_t asz = 16;
    {
        int gm = m0 + arow;
        if (GATHER == 1) {
            int pos = gm & 4095;
            if (pos < 4033) Aptr = A + (size_t)(gm + 63) * K;
            else { Aptr = A; asz = 0; }
        } else Aptr = A + (size_t)gm * K;
    }
    // B loader: row = t>>3 (0..31), offset (t&7)*16 halves
    const int bkr  = t >> 3;
    const int boff = (t & 7) * 16;               // halves
    const __half* Wptr = W + (size_t)bkr * N + n0 + boff;

    auto load_stage = [&](int i) {
        const int buf = i % FG_STAGES;
        const int k0  = i * 32;
        const uint32_t ab = sbase + buf * STAGE_B;
        cpa16(ab + arow * (A_STR_H * 2) + aoff * 2,     Aptr + k0 + aoff,     asz);
        cpa16(ab + arow * (A_STR_H * 2) + aoff * 2 + 16, Aptr + k0 + aoff + 8, asz);
        const uint32_t bb = ab + A_STAGE_B;
        cpa16(bb + bkr * (B_STR_H * 2) + boff * 2,      Wptr + (size_t)k0 * N,     16);
        cpa16(bb + bkr * (B_STR_H * 2) + boff * 2 + 16, Wptr + (size_t)k0 * N + 8, 16);
    };

    float acc[4][4][4];
    #pragma unroll
    for (int i = 0; i < 4; i++)
        #pragma unroll
        for (int j = 0; j < 4; j++)
            #pragma unroll
            for (int q = 0; q < 4; q++) acc[i][j][q] = 0.f;

    #pragma unroll
    for (int s = 0; s < FG_STAGES - 1; s++) { load_stage(s); CPA_COMMIT(); }

    // ldmatrix lane-derived indices
    const int a_lrow = lane & 15;                // row within 16-row tile
    const int a_lkof = (lane >> 4) << 3;         // 0 or 8 (k-offset)
    const int b_lrow = lane & 15;                // k-row within 16
    const int b_lnof = (lane >> 4) << 3;         // 0 or 8 (n-offset)

    for (int i = 0; i < kt; i++) {
        CPA_WAIT2();
        __syncthreads();
        if (i + FG_STAGES - 1 < kt) load_stage(i + FG_STAGES - 1);
        CPA_COMMIT();

        const uint32_t ab = sbase + (i % FG_STAGES) * STAGE_B;
        const uint32_t bb = ab + A_STAGE_B;

        #pragma unroll
        for (int kk0 = 0; kk0 < 32; kk0 += 16) {
            unsigned afr[4][4], bfr[4][2];
            #pragma unroll
            for (int ii = 0; ii < 4; ii++) {
                const uint32_t addr = ab
                    + (m_base + ii * 16 + a_lrow) * (A_STR_H * 2)
                    + (kk0 + a_lkof) * 2;
                ldsm_x4(afr[ii][0], afr[ii][1], afr[ii][2], afr[ii][3], addr);
            }
            #pragma unroll
            for (int jt2 = 0; jt2 < 2; jt2++) {
                const uint32_t addr = bb
                    + (kk0 + b_lrow) * (B_STR_H * 2)
                    + (n_base + jt2 * 16 + b_lnof) * 2;
                ldsm_x4t(bfr[jt2*2][0], bfr[jt2*2][1],
                         bfr[jt2*2+1][0], bfr[jt2*2+1][1], addr);
            }
            #pragma unroll
            for (int ii = 0; ii < 4; ii++)
                #pragma unroll
                for (int j = 0; j < 4; j++)
                    mma_f16(acc[ii][j], afr[ii], bfr[j]);
        }
        __syncthreads();
    }

    // epilogue (C fragment layout identical to m16n8k8)
    #pragma unroll
    for (int i = 0; i < 4; i++) {
        const int r0 = m0 + m_base + i * 16 + lg;
        const int r1 = r0 + 8;
        #pragma unroll
        for (int j = 0; j < 4; j++) {
            const int col = n0 + n_base + j * 8 + (lk << 1);
            if (EPI == 0) {
                *(float2*)(C + (size_t)r0 * N + col) = make_float2(acc[i][j][0], acc[i][j][1]);
                *(float2*)(C + (size_t)r1 * N + col) = make_float2(acc[i][j][2], acc[i][j][3]);
            } else {
                const float2 bvv = *(const float2*)(bias + col);
                int pos0 = r0 & 4095;
                if (pos0 < 4033) {
                    const int bb2 = r0 >> 12;
                    float* p = C + ((size_t)bb2 * 4096 + pos0 + 63) * N + col;
                    *(float2*)p = make_float2(acc[i][j][0] + bvv.x, acc[i][j][1] + bvv.y);
                }
                int pos1 = r1 & 4095;
                if (pos1 < 4033) {
                    const int bb2 = r1 >> 12;
                    float* p = C + ((size_t)bb2 * 4096 + pos1 + 63) * N + col;
                    *(float2*)p = make_float2(acc[i][j][2] + bvv.x, acc[i][j][3] + bvv.y);
                }
            }
        }
    }
}

// ---------------------------------------------------------------------------
// Fused attention (round-6 structure; output stored as fp16)
// ---------------------------------------------------------------------------
#define SIMW 324
#define ATTN_SMEM ((32*68 + 64*68 + 32*SIMW) * 4)

__global__ __launch_bounds__(256)
void attn_kernel(const float* __restrict__ Q, const float* __restrict__ Kb,
                 const float* __restrict__ Vb,
                 const float* __restrict__ qpe63,
                 const float* __restrict__ kpe,
                 const float* __restrict__ null_k,
                 const float* __restrict__ null_v,
                 __half* __restrict__ O)
{
    extern __shared__ float sm[];
    float* qs  = sm;                  // [32][68]
    float* kvs = qs + 32 * 68;        // [64][68]
    float* sim = kvs + 64 * 68;       // [32][SIMW]

    const int c    = blockIdx.x;
    const int h    = blockIdx.y;
    const int half = blockIdx.z;
    const int r0   = half * 32;
    const int t    = threadIdx.x;
    const int ty = t >> 4, tx = t & 15;
    const float scale = 0.125f;

    for (int e = t; e < 32 * 64; e += 256) {
        int i = e >> 6, d = e & 63;
        qs[i * 68 + d] = Q[((size_t)(c * 64 + r0 + i)) * INNER + h * 64 + d] * scale;
    }
    __syncthreads();

    if (half == 0) {
        float nq0 = 0.f;
        if (t < 64) {
            int d = t;
            float v = qs[d];
            float p = (d < 32) ? -qs[d + 32] : qs[d - 32];
            float f = qpe63[d];
            nq0 = v * cosf(f) + p * sinf(f);
        }
        __syncthreads();
        if (t < 64) qs[t] = nq0;
        __syncthreads();
    }

    for (int jt = 0; jt < 5; jt++) {
        for (int e = t; e < 64 * 64; e += 256) {
            int jj = e >> 6, d = e & 63;
            int j = jt * 64 + jj;
            float val = 0.f;
            if (j == 0)       val = null_k[h * 64 + d];
            else if (j < 257) val = Kb[((size_t)(c * 256 + j - 1)) * INNER + h * 64 + d];
            kvs[jj * 68 + d] = val;
        }
        __syncthreads();
        float nv[16];
        {
            int q = 0;
            for (int e = t; e < 64 * 64; e += 256, q++) {
                int jj = e >> 6, d = e & 63;
                int j = jt * 64 + jj;
                float val = kvs[jj * 68 + d];
                if (j >= 1 && j < 257) {
                    int kr = (j - 1) & 127;
                    float f = kpe[kr * 64 + d];
                    float p = (d < 32) ? -kvs[jj * 68 + d + 32] : kvs[jj * 68 + d - 32];
                    val = val * cosf(f) + p * sinf(f);
                }
                nv[q] = val;
            }
        }
        __syncthreads();
        {
            int q = 0;
            for (int e = t; e < 64 * 64; e += 256, q++) {
                int jj = e >> 6, d = e & 63;
                kvs[jj * 68 + d] = nv[q];
            }
        }
        __syncthreads();

        float s[2][4];
        #pragma unroll
        for (int i = 0; i < 2; i++)
            #pragma unroll
            for (int j = 0; j < 4; j++) s[i][j] = 0.f;
        for (int d = 0; d < 64; d++) {
            float a[2], b[4];
            #pragma unroll
            for (int i = 0; i < 2; i++) a[i] = qs[(ty * 2 + i) * 68 + d];
            #pragma unroll
            for (int j = 0; j < 4; j++) b[j] = kvs[(tx * 4 + j) * 68 + d];
            #pragma unroll
            for (int i = 0; i < 2; i++)
                #pragma unroll
                for (int j = 0; j < 4; j++) s[i][j] = fmaf(a[i], b[j], s[i][j]);
        }
        #pragma unroll
        for (int i = 0; i < 2; i++)
            #pragma unroll
            for (int j = 0; j < 4; j++)
                sim[(ty * 2 + i) * SIMW + jt * 64 + tx * 4 + j] = s[i][j];
        __syncthreads();
    }

    {
        const int warp = t >> 5, lanei = t & 31;
        for (int i = warp; i < 32; i += 8) {
            float* row = sim + i * SIMW;
            float mx = -1e30f;
            for (int j = lanei; j < 257; j += 32) mx = fmaxf(mx, row[j]);
            #pragma unroll
            for (int o = 16; o; o >>= 1) mx = fmaxf(mx, __shfl_xor_sync(~0u, mx, o));
            float sum = 0.f;
            for (int j = lanei; j < 257; j += 32) {
                float e = __expf(row[j] - mx);
                row[j] = e;
                sum += e;
            }
            #pragma unroll
            for (int o = 16; o; o >>= 1) sum += __shfl_xor_sync(~0u, sum, o);
            float inv = 1.f / sum;
            for (int j = lanei; j < 257; j += 32) row[j] *= inv;
        }
    }
    __syncthreads();

    float oacc[2][4];
    #pragma unroll
    for (int i = 0; i < 2; i++)
        #pragma unroll
        for (int j = 0; j < 4; j++) oacc[i][j] = 0.f;

    for (int jt = 0; jt < 5; jt++) {
        for (int e = t; e < 64 * 64; e += 256) {
            int jj = e >> 6, d = e & 63;
            int j = jt * 64 + jj;
            float val = 0.f;
            if (j == 0)       val = null_v[h * 64 + d];
            else if (j < 257) val = Vb[((size_t)(c * 256 + j - 1)) * INNER + h * 64 + d];
            kvs[jj * 68 + d] = val;
        }
        __syncthreads();

        const int jmax = (jt == 4) ? 1 : 64;
        for (int jj = 0; jj < jmax; jj++) {
            int j = jt * 64 + jj;
            float a[2], b[4];
            #pragma unroll
            for (int i = 0; i < 2; i++) a[i] = sim[(ty * 2 + i) * SIMW + j];
            #pragma unroll
            for (int d = 0; d < 4; d++) b[d] = kvs[jj * 68 + tx * 4 + d];
            #pragma unroll
            for (int i = 0; i < 2; i++)
                #pragma unroll
                for (int d = 0; d < 4; d++)
                    oacc[i][d] = fmaf(a[i], b[d], oacc[i][d]);
        }
        __syncthreads();
    }

    #pragma unroll
    for (int i = 0; i < 2; i++) {
        __half2 p0 = __floats2half2_rn(oacc[i][0], oacc[i][1]);
        __half2 p1 = __floats2half2_rn(oacc[i][2], oacc[i][3]);
        size_t idx = ((size_t)(c * 64 + r0 + ty * 2 + i)) * INNER + h * 64 + tx * 4;
        *(uint2*)&O[idx] = make_uint2(*(unsigned*)&p0, *(unsigned*)&p1);
    }
}

// ---------------------------------------------------------------------------
// Zero the first 63 token rows of each batch
// ---------------------------------------------------------------------------
__global__ void zero_prefix_kernel(float* __restrict__ out)
{
    size_t idx = (size_t)blockIdx.x * 256 + threadIdx.x;
    const size_t total = (size_t)4 * 63 * 1024;
    if (idx < total) {
        size_t b   = idx / (63 * 1024);
        size_t rem = idx % (63 * 1024);
        out[b * (size_t)4096 * 1024 + rem] = 0.f;
    }
}

// ---------------------------------------------------------------------------
// Launch
// ---------------------------------------------------------------------------
extern "C" void kernel_launch(void* const* d_in, const int* in_sizes, int n_in,
                              void* d_out, int out_size)
{
    const float* x        = (const float*)d_in[0];
    const float* context  = (const float*)d_in[1];
    const float* q_pos    = (const float*)d_in[2];
    const float* k_pos    = (const float*)d_in[3];
    const float* Wq       = (const float*)d_in[4];
    const float* Wk       = (const float*)d_in[5];
    const float* Wv       = (const float*)d_in[6];
    const float* Wo       = (const float*)d_in[7];
    const float* bo       = (const float*)d_in[8];
    const float* null_k   = (const float*)d_in[9];
    const float* null_v   = (const float*)d_in[10];
    float* out            = (float*)d_out;

    float *Qb, *Kb, *Vb;
    __half *Ob, *Xh, *Ch, *Wqh, *Wkh, *Wvh, *Woh;
    cudaGetSymbolAddress((void**)&Qb,  g_Q);
    cudaGetSymbolAddress((void**)&Kb,  g_K);
    cudaGetSymbolAddress((void**)&Vb,  g_V);
    cudaGetSymbolAddress((void**)&Ob,  g_O);
    cudaGetSymbolAddress((void**)&Xh,  g_xh);
    cudaGetSymbolAddress((void**)&Ch,  g_ch);
    cudaGetSymbolAddress((void**)&Wqh, g_wq);
    cudaGetSymbolAddress((void**)&Wkh, g_wk);
    cudaGetSymbolAddress((void**)&Wvh, g_wv);
    cudaGetSymbolAddress((void**)&Woh, g_wo);

    cudaFuncSetAttribute(f16_gemm<1,0>, cudaFuncAttributeMaxDynamicSharedMemorySize, FG_SMEM);
    cudaFuncSetAttribute(f16_gemm<0,0>, cudaFuncAttributeMaxDynamicSharedMemorySize, FG_SMEM);
    cudaFuncSetAttribute(f16_gemm<0,1>, cudaFuncAttributeMaxDynamicSharedMemorySize, FG_SMEM);
    cudaFuncSetAttribute(attn_kernel,   cudaFuncAttributeMaxDynamicSharedMemorySize, ATTN_SMEM);

    // fp32 -> fp16 conversions (paired launches)
    {
        int nw = (DIMM * INNER) / 4;   // 131072 float4 per weight
        cvt_f16_dual<<<(2*nw + 255) / 256, 256>>>(
            (const float4*)Wq, (uint2*)Wqh, nw, (const float4*)Wk, (uint2*)Wkh, nw);
        cvt_f16_dual<<<(2*nw + 255) / 256, 256>>>(
            (const float4*)Wv, (uint2*)Wvh, nw, (const float4*)Wo, (uint2*)Woh, nw);
        int nx4 = (NX * DIMM) / 4;
        int nc4 = (int)(((size_t)MKV * DIMM) / 4);
        cvt_f16_dual<<<(nx4 + nc4 + 255) / 256, 256>>>(
            (const float4*)x, (uint2*)Xh, nx4, (const float4*)context, (uint2*)Ch, nc4);
    }

    // Q = shifted-x @ Wq
    {
        dim3 grid(INNER / 128, MQ / 128);
        f16_gemm<1, 0><<<grid, 256, FG_SMEM>>>(Xh, Wqh, Qb, MQ, INNER, DIMM, nullptr);
    }
    // K = context @ Wk ; V = context @ Wv
    {
        dim3 grid(INNER / 128, MKV / 128);
        f16_gemm<0, 0><<<grid, 256, FG_SMEM>>>(Ch, Wkh, Kb, MKV, INNER, DIMM, nullptr);
        f16_gemm<0, 0><<<grid, 256, FG_SMEM>>>(Ch, Wvh, Vb, MKV, INNER, DIMM, nullptr);
    }
    // fused rope + attention (writes fp16)
    {
        dim3 grid(BK_CH, NH, 2);
        attn_kernel<<<grid, 256, ATTN_SMEM>>>(Qb, Kb, Vb,
                                              q_pos + 63 * 64, k_pos,
                                              null_k, null_v, Ob);
    }
    // out = attn_out @ Wo + bo, scattered with +63 shift
    {
        dim3 grid(DIMM / 128, MQ / 128);
        f16_gemm<0, 1><<<grid, 256, FG_SMEM>>>(Ob, Woh, out, MQ, DIMM, INNER, bo);
    }
    // zero first 63 rows per batch
    {
        const int total = 4 * 63 * 1024;
        zero_prefix_kernel<<<(total + 255) / 256, 256>>>(out);
    }
}

// round 10
// speedup vs baseline: 2.2468x; 1.0026x over previous
#include <cuda_runtime.h>
#include <cuda_fp16.h>
#include <math.h>
#include <stdint.h>

// ---------------------------------------------------------------------------
// Problem constants
// ---------------------------------------------------------------------------
#define DIMM   1024
#define INNER  512
#define BK_CH  256
#define NH     8
#define MQ     (BK_CH*64)       // 16384
#define MKV    (BK_CH*256)      // 65536
#define NX     (4*4096)

// ---------------------------------------------------------------------------
// Scratch
// ---------------------------------------------------------------------------
__device__ float  g_Q[(size_t)MQ * INNER];
__device__ float  g_K[(size_t)MKV * INNER];
__device__ float  g_V[(size_t)MKV * INNER];
__device__ __half g_O[(size_t)MQ * INNER];          // attn output (fp16)
__device__ __half g_xh[(size_t)NX * DIMM];
__device__ __half g_ch[(size_t)MKV * DIMM];
__device__ __half g_wq[(size_t)DIMM * INNER];
__device__ __half g_wk[(size_t)DIMM * INNER];
__device__ __half g_wv[(size_t)DIMM * INNER];
__device__ __half g_wo[(size_t)INNER * DIMM];

// ---------------------------------------------------------------------------
// helpers
// ---------------------------------------------------------------------------
__device__ __forceinline__ uint32_t smem_u32(const void* p) {
    uint32_t a;
    asm("{ .reg .u64 t; cvta.to.shared.u64 t, %1; cvt.u32.u64 %0, t; }" : "=r"(a) : "l"(p));
    return a;
}
__device__ __forceinline__ void mma_f16(float* c, const unsigned* a, const unsigned* b) {
    asm volatile(
        "mma.sync.aligned.m16n8k16.row.col.f32.f16.f16.f32 "
        "{%0,%1,%2,%3}, {%4,%5,%6,%7}, {%8,%9}, {%0,%1,%2,%3};\n"
        : "+f"(c[0]), "+f"(c[1]), "+f"(c[2]), "+f"(c[3])
        : "r"(a[0]), "r"(a[1]), "r"(a[2]), "r"(a[3]),
          "r"(b[0]), "r"(b[1]));
}
__device__ __forceinline__ void ldsm_x4(unsigned& r0, unsigned& r1,
                                        unsigned& r2, unsigned& r3, uint32_t a) {
    asm volatile("ldmatrix.sync.aligned.m8n8.x4.shared.b16 {%0,%1,%2,%3}, [%4];"
                 : "=r"(r0), "=r"(r1), "=r"(r2), "=r"(r3) : "r"(a));
}
__device__ __forceinline__ void ldsm_x4t(unsigned& r0, unsigned& r1,
                                         unsigned& r2, unsigned& r3, uint32_t a) {
    asm volatile("ldmatrix.sync.aligned.m8n8.x4.trans.shared.b16 {%0,%1,%2,%3}, [%4];"
                 : "=r"(r0), "=r"(r1), "=r"(r2), "=r"(r3) : "r"(a));
}
__device__ __forceinline__ void cpa16(uint32_t dst, const void* src, uint32_t ssize) {
    asm volatile("cp.async.cg.shared.global [%0], [%1], 16, %2;"
                 :: "r"(dst), "l"(src), "r"(ssize) : "memory");
}
#define CPA_COMMIT() asm volatile("cp.async.commit_group;" ::: "memory")
#define CPA_WAIT2()  asm volatile("cp.async.wait_group 2;" ::: "memory")

// ---------------------------------------------------------------------------
// Dual fp32 -> fp16 conversion (2 tensors per launch), float4 -> 4 halves
// ---------------------------------------------------------------------------
__global__ void cvt_f16_dual(const float4* __restrict__ in1, uint2* __restrict__ out1, int n1,
                             const float4* __restrict__ in2, uint2* __restrict__ out2, int n2)
{
    int i = blockIdx.x * blockDim.x + threadIdx.x;
    if (i < n1) {
        float4 v = in1[i];
        __half2 a = __floats2half2_rn(v.x, v.y);
        __half2 b = __floats2half2_rn(v.z, v.w);
        out1[i] = make_uint2(*(unsigned*)&a, *(unsigned*)&b);
    } else if (i - n1 < n2) {
        int j = i - n1;
        float4 v = in2[j];
        __half2 a = __floats2half2_rn(v.x, v.y);
        __half2 b = __floats2half2_rn(v.z, v.w);
        out2[j] = make_uint2(*(unsigned*)&a, *(unsigned*)&b);
    }
}

// ---------------------------------------------------------------------------
// FP16 GEMM: C[M,N] = A[M,K] @ W[K,N], fp32 accumulate.
// BM=128, BN=128, BK=32; 4-stage cp.async; 256 threads (8 warps 2x4),
// warp tile 64x32 (m16n8k16). ldmatrix for both fragments.
// A smem [m][k] stride 40 halves (80B); B smem [k][n] stride 136 halves (272B).
// ---------------------------------------------------------------------------
#define FG_STAGES 4
#define A_STR_H  40
#define B_STR_H  136
#define A_STAGE_B (128 * A_STR_H * 2)           // 10240
#define B_STAGE_B (32 * B_STR_H * 2)            // 8704
#define STAGE_B   (A_STAGE_B + B_STAGE_B)       // 18944
#define FG_SMEM   (FG_STAGES * STAGE_B)         // 75776

template<int GATHER, int EPI>
__global__ __launch_bounds__(256, 2)
void f16_gemm(const __half* __restrict__ A, const __half* __restrict__ W,
              float* __restrict__ C, int M, int N, int K,
              const float* __restrict__ bias)
{
    extern __shared__ char smc[];
    const uint32_t sbase = smem_u32(smc);

    const int n0 = blockIdx.x * 128;
    const int m0 = blockIdx.y * 128;
    const int t  = threadIdx.x;
    const int lane = t & 31;
    const int warp = t >> 5;
    const int m_base = (warp >> 2) * 64;
    const int n_base = (warp & 3) * 32;
    const int lg = lane >> 2;
    const int lk = lane & 3;
    const int kt = K / 32;

    // A loader: row = t>>1, byte-offset (t&1)*32 within the 64B row
    const int arow = t >> 1;
    const int aoff = (t & 1) * 16;               // halves
    const __half* Aptr; uint32_t asz = 16;
    {
        int gm = m0 + arow;
        if (GATHER == 1) {
            int pos = gm & 4095;
            if (pos < 4033) Aptr = A + (size_t)(gm + 63) * K;
            else { Aptr = A; asz = 0; }
        } else Aptr = A + (size_t)gm * K;
    }
    // B loader: row = t>>3 (0..31), offset (t&7)*16 halves
    const int bkr  = t >> 3;
    const int boff = (t & 7) * 16;               // halves
    const __half* Wptr = W + (size_t)bkr * N + n0 + boff;

    auto load_stage = [&](int i) {
        const int buf = i % FG_STAGES;
        const int k0  = i * 32;
        const uint32_t ab = sbase + buf * STAGE_B;
        cpa16(ab + arow * (A_STR_H * 2) + aoff * 2,     Aptr + k0 + aoff,     asz);
        cpa16(ab + arow * (A_STR_H * 2) + aoff * 2 + 16, Aptr + k0 + aoff + 8, asz);
        const uint32_t bb = ab + A_STAGE_B;
        cpa16(bb + bkr * (B_STR_H * 2) + boff * 2,      Wptr + (size_t)k0 * N,     16);
        cpa16(bb + bkr * (B_STR_H * 2) + boff * 2 + 16, Wptr + (size_t)k0 * N + 8, 16);
    };

    float acc[4][4][4];
    #pragma unroll
    for (int i = 0; i < 4; i++)
        #pragma unroll
        for (int j = 0; j < 4; j++)
            #pragma unroll
            for (int q = 0; q < 4; q++) acc[i][j][q] = 0.f;

    #pragma unroll
    for (int s = 0; s < FG_STAGES - 1; s++) { load_stage(s); CPA_COMMIT(); }

    // ldmatrix lane-derived indices
    const int a_lrow = lane & 15;                // row within 16-row tile
    const int a_lkof = (lane >> 4) << 3;         // 0 or 8 (k-offset)
    const int b_lrow = lane & 15;                // k-row within 16
    const int b_lnof = (lane >> 4) << 3;         // 0 or 8 (n-offset)

    for (int i = 0; i < kt; i++) {
        CPA_WAIT2();
        __syncthreads();
        if (i + FG_STAGES - 1 < kt) load_stage(i + FG_STAGES - 1);
        CPA_COMMIT();

        const uint32_t ab = sbase + (i % FG_STAGES) * STAGE_B;
        const uint32_t bb = ab + A_STAGE_B;

        #pragma unroll
        for (int kk0 = 0; kk0 < 32; kk0 += 16) {
            unsigned afr[4][4], bfr[4][2];
            #pragma unroll
            for (int ii = 0; ii < 4; ii++) {
                const uint32_t addr = ab
                    + (m_base + ii * 16 + a_lrow) * (A_STR_H * 2)
                    + (kk0 + a_lkof) * 2;
                ldsm_x4(afr[ii][0], afr[ii][1], afr[ii][2], afr[ii][3], addr);
            }
            #pragma unroll
            for (int jt2 = 0; jt2 < 2; jt2++) {
                const uint32_t addr = bb
                    + (kk0 + b_lrow) * (B_STR_H * 2)
                    + (n_base + jt2 * 16 + b_lnof) * 2;
                ldsm_x4t(bfr[jt2*2][0], bfr[jt2*2][1],
                         bfr[jt2*2+1][0], bfr[jt2*2+1][1], addr);
            }
            #pragma unroll
            for (int ii = 0; ii < 4; ii++)
                #pragma unroll
                for (int j = 0; j < 4; j++)
                    mma_f16(acc[ii][j], afr[ii], bfr[j]);
        }
        __syncthreads();
    }

    // epilogue (C fragment layout identical to m16n8k8)
    #pragma unroll
    for (int i = 0; i < 4; i++) {
        const int r0 = m0 + m_base + i * 16 + lg;
        const int r1 = r0 + 8;
        #pragma unroll
        for (int j = 0; j < 4; j++) {
            const int col = n0 + n_base + j * 8 + (lk << 1);
            if (EPI == 0) {
                *(float2*)(C + (size_t)r0 * N + col) = make_float2(acc[i][j][0], acc[i][j][1]);
                *(float2*)(C + (size_t)r1 * N + col) = make_float2(acc[i][j][2], acc[i][j][3]);
            } else {
                const float2 bvv = *(const float2*)(bias + col);
                int pos0 = r0 & 4095;
                if (pos0 < 4033) {
                    const int bb2 = r0 >> 12;
                    float* p = C + ((size_t)bb2 * 4096 + pos0 + 63) * N + col;
                    *(float2*)p = make_float2(acc[i][j][0] + bvv.x, acc[i][j][1] + bvv.y);
                }
                int pos1 = r1 & 4095;
                if (pos1 < 4033) {
                    const int bb2 = r1 >> 12;
                    float* p = C + ((size_t)bb2 * 4096 + pos1 + 63) * N + col;
                    *(float2*)p = make_float2(acc[i][j][2] + bvv.x, acc[i][j][3] + bvv.y);
                }
            }
        }
    }
}

// ---------------------------------------------------------------------------
// Fused attention (round-6 structure; output stored as fp16)
// ---------------------------------------------------------------------------
#define SIMW 324
#define ATTN_SMEM ((32*68 + 64*68 + 32*SIMW) * 4)

__global__ __launch_bounds__(256)
void attn_kernel(const float* __restrict__ Q, const float* __restrict__ Kb,
                 const float* __restrict__ Vb,
                 const float* __restrict__ qpe63,
                 const float* __restrict__ kpe,
                 const float* __restrict__ null_k,
                 const float* __restrict__ null_v,
                 __half* __restrict__ O)
{
    extern __shared__ float sm[];
    float* qs  = sm;                  // [32][68]
    float* kvs = qs + 32 * 68;        // [64][68]
    float* sim = kvs + 64 * 68;       // [32][SIMW]

    const int c    = blockIdx.x;
    const int h    = blockIdx.y;
    const int half = blockIdx.z;
    const int r0   = half * 32;
    const int t    = threadIdx.x;
    const int ty = t >> 4, tx = t & 15;
    const float scale = 0.125f;

    for (int e = t; e < 32 * 64; e += 256) {
        int i = e >> 6, d = e & 63;
        qs[i * 68 + d] = Q[((size_t)(c * 64 + r0 + i)) * INNER + h * 64 + d] * scale;
    }
    __syncthreads();

    if (half == 0) {
        float nq0 = 0.f;
        if (t < 64) {
            int d = t;
            float v = qs[d];
            float p = (d < 32) ? -qs[d + 32] : qs[d - 32];
            float f = qpe63[d];
            nq0 = v * cosf(f) + p * sinf(f);
        }
        __syncthreads();
        if (t < 64) qs[t] = nq0;
        __syncthreads();
    }

    for (int jt = 0; jt < 5; jt++) {
        for (int e = t; e < 64 * 64; e += 256) {
            int jj = e >> 6, d = e & 63;
            int j = jt * 64 + jj;
            float val = 0.f;
            if (j == 0)       val = null_k[h * 64 + d];
            else if (j < 257) val = Kb[((size_t)(c * 256 + j - 1)) * INNER + h * 64 + d];
            kvs[jj * 68 + d] = val;
        }
        __syncthreads();
        float nv[16];
        {
            int q = 0;
            for (int e = t; e < 64 * 64; e += 256, q++) {
                int jj = e >> 6, d = e & 63;
                int j = jt * 64 + jj;
                float val = kvs[jj * 68 + d];
                if (j >= 1 && j < 257) {
                    int kr = (j - 1) & 127;
                    float f = kpe[kr * 64 + d];
                    float p = (d < 32) ? -kvs[jj * 68 + d + 32] : kvs[jj * 68 + d - 32];
                    val = val * cosf(f) + p * sinf(f);
                }
                nv[q] = val;
            }
        }
        __syncthreads();
        {
            int q = 0;
            for (int e = t; e < 64 * 64; e += 256, q++) {
                int jj = e >> 6, d = e & 63;
                kvs[jj * 68 + d] = nv[q];
            }
        }
        __syncthreads();

        float s[2][4];
        #pragma unroll
        for (int i = 0; i < 2; i++)
            #pragma unroll
            for (int j = 0; j < 4; j++) s[i][j] = 0.f;
        for (int d = 0; d < 64; d++) {
            float a[2], b[4];
            #pragma unroll
            for (int i = 0; i < 2; i++) a[i] = qs[(ty * 2 + i) * 68 + d];
            #pragma unroll
            for (int j = 0; j < 4; j++) b[j] = kvs[(tx * 4 + j) * 68 + d];
            #pragma unroll
            for (int i = 0; i < 2; i++)
                #pragma unroll
                for (int j = 0; j < 4; j++) s[i][j] = fmaf(a[i], b[j], s[i][j]);
        }
        #pragma unroll
        for (int i = 0; i < 2; i++)
            #pragma unroll
            for (int j = 0; j < 4; j++)
                sim[(ty * 2 + i) * SIMW + jt * 64 + tx * 4 + j] = s[i][j];
        __syncthreads();
    }

    {
        const int warp = t >> 5, lanei = t & 31;
        for (int i = warp; i < 32; i += 8) {
            float* row = sim + i * SIMW;
            float mx = -1e30f;
            for (int j = lanei; j < 257; j += 32) mx = fmaxf(mx, row[j]);
            #pragma unroll
            for (int o = 16; o; o >>= 1) mx = fmaxf(mx, __shfl_xor_sync(~0u, mx, o));
            float sum = 0.f;
            for (int j = lanei; j < 257; j += 32) {
                float e = __expf(row[j] - mx);
                row[j] = e;
                sum += e;
            }
            #pragma unroll
            for (int o = 16; o; o >>= 1) sum += __shfl_xor_sync(~0u, sum, o);
            float inv = 1.f / sum;
            for (int j = lanei; j < 257; j += 32) row[j] *= inv;
        }
    }
    __syncthreads();

    float oacc[2][4];
    #pragma unroll
    for (int i = 0; i < 2; i++)
        #pragma unroll
        for (int j = 0; j < 4; j++) oacc[i][j] = 0.f;

    for (int jt = 0; jt < 5; jt++) {
        for (int e = t; e < 64 * 64; e += 256) {
            int jj = e >> 6, d = e & 63;
            int j = jt * 64 + jj;
            float val = 0.f;
            if (j == 0)       val = null_v[h * 64 + d];
            else if (j < 257) val = Vb[((size_t)(c * 256 + j - 1)) * INNER + h * 64 + d];
            kvs[jj * 68 + d] = val;
        }
        __syncthreads();

        const int jmax = (jt == 4) ? 1 : 64;
        for (int jj = 0; jj < jmax; jj++) {
            int j = jt * 64 + jj;
            float a[2], b[4];
            #pragma unroll
            for (int i = 0; i < 2; i++) a[i] = sim[(ty * 2 + i) * SIMW + j];
            #pragma unroll
            for (int d = 0; d < 4; d++) b[d] = kvs[jj * 68 + tx * 4 + d];
            #pragma unroll
            for (int i = 0; i < 2; i++)
                #pragma unroll
                for (int d = 0; d < 4; d++)
                    oacc[i][d] = fmaf(a[i], b[d], oacc[i][d]);
        }
        __syncthreads();
    }

    #pragma unroll
    for (int i = 0; i < 2; i++) {
        __half2 p0 = __floats2half2_rn(oacc[i][0], oacc[i][1]);
        __half2 p1 = __floats2half2_rn(oacc[i][2], oacc[i][3]);
        size_t idx = ((size_t)(c * 64 + r0 + ty * 2 + i)) * INNER + h * 64 + tx * 4;
        *(uint2*)&O[idx] = make_uint2(*(unsigned*)&p0, *(unsigned*)&p1);
    }
}

// ---------------------------------------------------------------------------
// Zero the first 63 token rows of each batch
// ---------------------------------------------------------------------------
__global__ void zero_prefix_kernel(float* __restrict__ out)
{
    size_t idx = (size_t)blockIdx.x * 256 + threadIdx.x;
    const size_t total = (size_t)4 * 63 * 1024;
    if (idx < total) {
        size_t b   = idx / (63 * 1024);
        size_t rem = idx % (63 * 1024);
        out[b * (size_t)4096 * 1024 + rem] = 0.f;
    }
}

// ---------------------------------------------------------------------------
// Launch
// ---------------------------------------------------------------------------
extern "C" void kernel_launch(void* const* d_in, const int* in_sizes, int n_in,
                              void* d_out, int out_size)
{
    const float* x        = (const float*)d_in[0];
    const float* context  = (const float*)d_in[1];
    const float* q_pos    = (const float*)d_in[2];
    const float* k_pos    = (const float*)d_in[3];
    const float* Wq       = (const float*)d_in[4];
    const float* Wk       = (const float*)d_in[5];
    const float* Wv       = (const float*)d_in[6];
    const float* Wo       = (const float*)d_in[7];
    const float* bo       = (const float*)d_in[8];
    const float* null_k   = (const float*)d_in[9];
    const float* null_v   = (const float*)d_in[10];
    float* out            = (float*)d_out;

    float *Qb, *Kb, *Vb;
    __half *Ob, *Xh, *Ch, *Wqh, *Wkh, *Wvh, *Woh;
    cudaGetSymbolAddress((void**)&Qb,  g_Q);
    cudaGetSymbolAddress((void**)&Kb,  g_K);
    cudaGetSymbolAddress((void**)&Vb,  g_V);
    cudaGetSymbolAddress((void**)&Ob,  g_O);
    cudaGetSymbolAddress((void**)&Xh,  g_xh);
    cudaGetSymbolAddress((void**)&Ch,  g_ch);
    cudaGetSymbolAddress((void**)&Wqh, g_wq);
    cudaGetSymbolAddress((void**)&Wkh, g_wk);
    cudaGetSymbolAddress((void**)&Wvh, g_wv);
    cudaGetSymbolAddress((void**)&Woh, g_wo);

    cudaFuncSetAttribute(f16_gemm<1,0>, cudaFuncAttributeMaxDynamicSharedMemorySize, FG_SMEM);
    cudaFuncSetAttribute(f16_gemm<0,0>, cudaFuncAttributeMaxDynamicSharedMemorySize, FG_SMEM);
    cudaFuncSetAttribute(f16_gemm<0,1>, cudaFuncAttributeMaxDynamicSharedMemorySize, FG_SMEM);
    cudaFuncSetAttribute(attn_kernel,   cudaFuncAttributeMaxDynamicSharedMemorySize, ATTN_SMEM);

    // fp32 -> fp16 conversions (paired launches)
    {
        int nw = (DIMM * INNER) / 4;   // 131072 float4 per weight
        cvt_f16_dual<<<(2*nw + 255) / 256, 256>>>(
            (const float4*)Wq, (uint2*)Wqh, nw, (const float4*)Wk, (uint2*)Wkh, nw);
        cvt_f16_dual<<<(2*nw + 255) / 256, 256>>>(
            (const float4*)Wv, (uint2*)Wvh, nw, (const float4*)Wo, (uint2*)Woh, nw);
        int nx4 = (NX * DIMM) / 4;
        int nc4 = (int)(((size_t)MKV * DIMM) / 4);
        cvt_f16_dual<<<(nx4 + nc4 + 255) / 256, 256>>>(
            (const float4*)x, (uint2*)Xh, nx4, (const float4*)context, (uint2*)Ch, nc4);
    }

    // Q = shifted-x @ Wq
    {
        dim3 grid(INNER / 128, MQ / 128);
        f16_gemm<1, 0><<<grid, 256, FG_SMEM>>>(Xh, Wqh, Qb, MQ, INNER, DIMM, nullptr);
    }
    // K = context @ Wk ; V = context @ Wv
    {
        dim3 grid(INNER / 128, MKV / 128);
        f16_gemm<0, 0><<<grid, 256, FG_SMEM>>>(Ch, Wkh, Kb, MKV, INNER, DIMM, nullptr);
        f16_gemm<0, 0><<<grid, 256, FG_SMEM>>>(Ch, Wvh, Vb, MKV, INNER, DIMM, nullptr);
    }
    // fused rope + attention (writes fp16)
    {
        dim3 grid(BK_CH, NH, 2);
        attn_kernel<<<grid, 256, ATTN_SMEM>>>(Qb, Kb, Vb,
                                              q_pos + 63 * 64, k_pos,
                                              null_k, null_v, Ob);
    }
    // out = attn_out @ Wo + bo, scattered with +63 shift
    {
        dim3 grid(DIMM / 128, MQ / 128);
        f16_gemm<0, 1><<<grid, 256, FG_SMEM>>>(Ob, Woh, out, MQ, DIMM, INNER, bo);
    }
    // zero first 63 rows per batch
    {
        const int total = 4 * 63 * 1024;
        zero_prefix_kernel<<<(total + 255) / 256, 256>>>(out);
    }
}

// round 11
// speedup vs baseline: 4.4791x; 1.9936x over previous
#include <cuda_runtime.h>
#include <cuda_fp16.h>
#include <math.h>
#include <stdint.h>

// ---------------------------------------------------------------------------
// Problem constants
// ---------------------------------------------------------------------------
#define DIMM   1024
#define INNER  512
#define BK_CH  256
#define NH     8
#define MQ     (BK_CH*64)       // 16384
#define MKV    (BK_CH*256)      // 65536
#define NX     (4*4096)

// ---------------------------------------------------------------------------
// Scratch
// ---------------------------------------------------------------------------
__device__ __half g_Qh[(size_t)MQ * INNER];
__device__ __half g_Kh[(size_t)MKV * INNER];
__device__ __half g_Vh[(size_t)MKV * INNER];
__device__ __half g_O[(size_t)MQ * INNER];
__device__ __half g_xh[(size_t)NX * DIMM];
__device__ __half g_ch[(size_t)MKV * DIMM];
__device__ __half g_wq[(size_t)DIMM * INNER];
__device__ __half g_wk[(size_t)DIMM * INNER];
__device__ __half g_wv[(size_t)DIMM * INNER];
__device__ __half g_wo[(size_t)INNER * DIMM];
__device__ float  g_kcos[128 * 64];
__device__ float  g_ksin[128 * 64];

// ---------------------------------------------------------------------------
// helpers
// ---------------------------------------------------------------------------
__device__ __forceinline__ uint32_t smem_u32(const void* p) {
    uint32_t a;
    asm("{ .reg .u64 t; cvta.to.shared.u64 t, %1; cvt.u32.u64 %0, t; }" : "=r"(a) : "l"(p));
    return a;
}
__device__ __forceinline__ void mma_f16(float* c, const unsigned* a, const unsigned* b) {
    asm volatile(
        "mma.sync.aligned.m16n8k16.row.col.f32.f16.f16.f32 "
        "{%0,%1,%2,%3}, {%4,%5,%6,%7}, {%8,%9}, {%0,%1,%2,%3};\n"
        : "+f"(c[0]), "+f"(c[1]), "+f"(c[2]), "+f"(c[3])
        : "r"(a[0]), "r"(a[1]), "r"(a[2]), "r"(a[3]),
          "r"(b[0]), "r"(b[1]));
}
__device__ __forceinline__ void ldsm_x4(unsigned& r0, unsigned& r1,
                                        unsigned& r2, unsigned& r3, uint32_t a) {
    asm volatile("ldmatrix.sync.aligned.m8n8.x4.shared.b16 {%0,%1,%2,%3}, [%4];"
                 : "=r"(r0), "=r"(r1), "=r"(r2), "=r"(r3) : "r"(a));
}
__device__ __forceinline__ void ldsm_x4t(unsigned& r0, unsigned& r1,
                                         unsigned& r2, unsigned& r3, uint32_t a) {
    asm volatile("ldmatrix.sync.aligned.m8n8.x4.trans.shared.b16 {%0,%1,%2,%3}, [%4];"
                 : "=r"(r0), "=r"(r1), "=r"(r2), "=r"(r3) : "r"(a));
}
__device__ __forceinline__ void cpa16(uint32_t dst, const void* src, uint32_t ssize) {
    asm volatile("cp.async.cg.shared.global [%0], [%1], 16, %2;"
                 :: "r"(dst), "l"(src), "r"(ssize) : "memory");
}
#define CPA_COMMIT() asm volatile("cp.async.commit_group;" ::: "memory")
#define CPA_WAIT2()  asm volatile("cp.async.wait_group 2;" ::: "memory")

// ---------------------------------------------------------------------------
// Conversions + RoPE preprocessing
// ---------------------------------------------------------------------------
__global__ void cvt_f16_dual(const float4* __restrict__ in1, uint2* __restrict__ out1, int n1,
                             const float4* __restrict__ in2, uint2* __restrict__ out2, int n2)
{
    int i = blockIdx.x * blockDim.x + threadIdx.x;
    if (i < n1) {
        float4 v = in1[i];
        __half2 a = __floats2half2_rn(v.x, v.y);
        __half2 b = __floats2half2_rn(v.z, v.w);
        out1[i] = make_uint2(*(unsigned*)&a, *(unsigned*)&b);
    } else if (i - n1 < n2) {
        int j = i - n1;
        float4 v = in2[j];
        __half2 a = __floats2half2_rn(v.x, v.y);
        __half2 b = __floats2half2_rn(v.z, v.w);
        out2[j] = make_uint2(*(unsigned*)&a, *(unsigned*)&b);
    }
}

__global__ void rope_tab_kernel(const float* __restrict__ kpe,
                                float* __restrict__ kc, float* __restrict__ ks)
{
    int i = blockIdx.x * 256 + threadIdx.x;
    if (i < 128 * 64) { float f = kpe[i]; kc[i] = cosf(f); ks[i] = sinf(f); }
}

// In-place RoPE on the whole fp16 K tensor. One thread handles pair (d, d+32).
__global__ void rope_k_kernel(__half* __restrict__ Kh,
                              const float* __restrict__ kc, const float* __restrict__ ks)
{
    size_t idx = (size_t)blockIdx.x * 256 + threadIdx.x;   // 16,777,216 total
    int d = (int)(idx & 31);
    int h = (int)((idx >> 5) & 7);
    size_t row = idx >> 8;
    int kr = (int)(row & 127);
    size_t base = row * INNER + h * 64;
    float k1 = __half2float(Kh[base + d]);
    float k2 = __half2float(Kh[base + d + 32]);
    float c1 = kc[kr * 64 + d],      s1 = ks[kr * 64 + d];
    float c2 = kc[kr * 64 + d + 32], s2 = ks[kr * 64 + d + 32];
    Kh[base + d]      = __float2half(k1 * c1 - k2 * s1);
    Kh[base + d + 32] = __float2half(k2 * c2 + k1 * s2);
}

// In-place RoPE on Q chunk-row 0 (rows c*64), qpe63 angles.
__global__ void rope_q_kernel(__half* __restrict__ Qh, const float* __restrict__ qpe63)
{
    int idx = blockIdx.x * 256 + threadIdx.x;              // 65536 total
    int d = idx & 31;
    int h = (idx >> 5) & 7;
    int c = idx >> 8;
    size_t base = (size_t)(c * 64) * INNER + h * 64;
    float q1 = __half2float(Qh[base + d]);
    float q2 = __half2float(Qh[base + d + 32]);
    float f1 = qpe63[d], f2 = qpe63[d + 32];
    Qh[base + d]      = __float2half(q1 * cosf(f1) - q2 * sinf(f1));
    Qh[base + d + 32] = __float2half(q2 * cosf(f2) + q1 * sinf(f2));
}

// ---------------------------------------------------------------------------
// FP16 GEMM (round-10 structure), OUTH: fp16 output, alpha scale.
// ---------------------------------------------------------------------------
#define FG_STAGES 4
#define A_STR_H  40
#define B_STR_H  136
#define A_STAGE_B (128 * A_STR_H * 2)
#define B_STAGE_B (32 * B_STR_H * 2)
#define STAGE_B   (A_STAGE_B + B_STAGE_B)
#define FG_SMEM   (FG_STAGES * STAGE_B)

template<int GATHER, int EPI, int OUTH>
__global__ __launch_bounds__(256, 2)
void f16_gemm(const __half* __restrict__ A, const __half* __restrict__ W,
              void* __restrict__ Cv, int M, int N, int K,
              const float* __restrict__ bias, float alpha)
{
    extern __shared__ char smc[];
    const uint32_t sbase = smem_u32(smc);

    const int n0 = blockIdx.x * 128;
    const int m0 = blockIdx.y * 128;
    const int t  = threadIdx.x;
    const int lane = t & 31;
    const int warp = t >> 5;
    const int m_base = (warp >> 2) * 64;
    const int n_base = (warp & 3) * 32;
    const int lg = lane >> 2;
    const int lk = lane & 3;
    const int kt = K / 32;

    const int arow = t >> 1;
    const int aoff = (t & 1) * 16;
    const __half* Aptr; uint32_t asz = 16;
    {
        int gm = m0 + arow;
        if (GATHER == 1) {
            int pos = gm & 4095;
            if (pos < 4033) Aptr = A + (size_t)(gm + 63) * K;
            else { Aptr = A; asz = 0; }
        } else Aptr = A + (size_t)gm * K;
    }
    const int bkr  = t >> 3;
    const int boff = (t & 7) * 16;
    const __half* Wptr = W + (size_t)bkr * N + n0 + boff;

    auto load_stage = [&](int i) {
        const int buf = i % FG_STAGES;
        const int k0  = i * 32;
        const uint32_t ab = sbase + buf * STAGE_B;
        cpa16(ab + arow * (A_STR_H * 2) + aoff * 2,      Aptr + k0 + aoff,     asz);
        cpa16(ab + arow * (A_STR_H * 2) + aoff * 2 + 16, Aptr + k0 + aoff + 8, asz);
        const uint32_t bb = ab + A_STAGE_B;
        cpa16(bb + bkr * (B_STR_H * 2) + boff * 2,      Wptr + (size_t)k0 * N,     16);
        cpa16(bb + bkr * (B_STR_H * 2) + boff * 2 + 16, Wptr + (size_t)k0 * N + 8, 16);
    };

    float acc[4][4][4];
    #pragma unroll
    for (int i = 0; i < 4; i++)
        #pragma unroll
        for (int j = 0; j < 4; j++)
            #pragma unroll
            for (int q = 0; q < 4; q++) acc[i][j][q] = 0.f;

    #pragma unroll
    for (int s = 0; s < FG_STAGES - 1; s++) { load_stage(s); CPA_COMMIT(); }

    const int a_lrow = lane & 15;
    const int a_lkof = (lane >> 4) << 3;

    for (int i = 0; i < kt; i++) {
        CPA_WAIT2();
        __syncthreads();
        if (i + FG_STAGES - 1 < kt) load_stage(i + FG_STAGES - 1);
        CPA_COMMIT();

        const uint32_t ab = sbase + (i % FG_STAGES) * STAGE_B;
        const uint32_t bb = ab + A_STAGE_B;

        #pragma unroll
        for (int kk0 = 0; kk0 < 32; kk0 += 16) {
            unsigned afr[4][4], bfr[4][2];
            #pragma unroll
            for (int ii = 0; ii < 4; ii++) {
                const uint32_t addr = ab
                    + (m_base + ii * 16 + a_lrow) * (A_STR_H * 2)
                    + (kk0 + a_lkof) * 2;
                ldsm_x4(afr[ii][0], afr[ii][1], afr[ii][2], afr[ii][3], addr);
            }
            #pragma unroll
            for (int jt2 = 0; jt2 < 2; jt2++) {
                const uint32_t addr = bb
                    + (kk0 + a_lrow) * (B_STR_H * 2)
                    + (n_base + jt2 * 16 + a_lkof) * 2;
                ldsm_x4t(bfr[jt2*2][0], bfr[jt2*2][1],
                         bfr[jt2*2+1][0], bfr[jt2*2+1][1], addr);
            }
            #pragma unroll
            for (int ii = 0; ii < 4; ii++)
                #pragma unroll
                for (int j = 0; j < 4; j++)
                    mma_f16(acc[ii][j], afr[ii], bfr[j]);
        }
        __syncthreads();
    }

    #pragma unroll
    for (int i = 0; i < 4; i++) {
        const int r0 = m0 + m_base + i * 16 + lg;
        const int r1 = r0 + 8;
        #pragma unroll
        for (int j = 0; j < 4; j++) {
            const int col = n0 + n_base + j * 8 + (lk << 1);
            if (OUTH == 1) {
                __half* C = (__half*)Cv;
                __half2 p0 = __floats2half2_rn(acc[i][j][0] * alpha, acc[i][j][1] * alpha);
                __half2 p1 = __floats2half2_rn(acc[i][j][2] * alpha, acc[i][j][3] * alpha);
                *(unsigned*)(C + (size_t)r0 * N + col) = *(unsigned*)&p0;
                *(unsigned*)(C + (size_t)r1 * N + col) = *(unsigned*)&p1;
            } else if (EPI == 0) {
                float* C = (float*)Cv;
                *(float2*)(C + (size_t)r0 * N + col) = make_float2(acc[i][j][0], acc[i][j][1]);
                *(float2*)(C + (size_t)r1 * N + col) = make_float2(acc[i][j][2], acc[i][j][3]);
            } else {
                float* C = (float*)Cv;
                const float2 bvv = *(const float2*)(bias + col);
                int pos0 = r0 & 4095;
                if (pos0 < 4033) {
                    const int bb2 = r0 >> 12;
                    float* p = C + ((size_t)bb2 * 4096 + pos0 + 63) * N + col;
                    *(float2*)p = make_float2(acc[i][j][0] + bvv.x, acc[i][j][1] + bvv.y);
                }
                int pos1 = r1 & 4095;
                if (pos1 < 4033) {
                    const int bb2 = r1 >> 12;
                    float* p = C + ((size_t)bb2 * 4096 + pos1 + 63) * N + col;
                    *(float2*)p = make_float2(acc[i][j][2] + bvv.x, acc[i][j][3] + bvv.y);
                }
            }
        }
    }
}

// ---------------------------------------------------------------------------
// Tensor-core attention: block = (chunk, head, half32). 256 threads, 8 warps.
// Q,K,V pre-roped fp16. S fp32 smem, softmax in regs, P fp16, PV via mma.
// smem: Q[32][72]h | KV[64][72]h | S[32][264]f | P[32][328]h = 68608 B
// ---------------------------------------------------------------------------
#define AT_Q_OFF  0
#define AT_KV_OFF 4608
#define AT_S_OFF  13824
#define AT_P_OFF  47616
#define AT_SMEM   68608

__global__ __launch_bounds__(256)
void attn_kernel(const __half* __restrict__ Qh, const __half* __restrict__ Kh,
                 const __half* __restrict__ Vh,
                 const float* __restrict__ null_k,
                 const float* __restrict__ null_v,
                 __half* __restrict__ O)
{
    extern __shared__ char smc[];
    __half* qsm = (__half*)(smc + AT_Q_OFF);    // [32][72]
    __half* kvm = (__half*)(smc + AT_KV_OFF);   // [64][72] (K transposed [d][kv] / V [kv][d])
    float*  S   = (float*) (smc + AT_S_OFF);    // [32][264]
    __half* P   = (__half*)(smc + AT_P_OFF);    // [32][328]
    const uint32_t qb = smem_u32(qsm);
    const uint32_t kb = smem_u32(kvm);
    const uint32_t pb = smem_u32(P);

    const int c    = blockIdx.x;
    const int h    = blockIdx.y;
    const int r0   = blockIdx.z * 32;
    const int t    = threadIdx.x;
    const int lane = t & 31;
    const int warp = t >> 5;
    const int wm = warp >> 2;        // 0..1 (16 rows each)
    const int wn = warp & 3;         // 0..3 (16 cols each)
    const int lg = lane >> 2, lk = lane & 3;
    const int lr = lane & 15, lo = (lane >> 4) << 3;

    // ---- load Q tile (pre-scaled, pre-roped) ----
    {
        int e = t;   // 256 threads, 256 uint4 loads (32 rows x 8 groups)
        int i = e >> 3, c8 = (e & 7) * 8;
        uint4 v = *(const uint4*)(Qh + ((size_t)(c * 64 + r0 + i)) * INNER + h * 64 + c8);
        *(uint4*)(qsm + i * 72 + c8) = v;
    }
    __syncthreads();

    // ---- S = Q @ K^T over 5 kv tiles ----
    for (int jt = 0; jt < 5; jt++) {
        // load K tile transposed: kvm[d][jj]
        for (int e = t; e < 512; e += 256) {
            int jj = e & 63, d0 = (e >> 6) * 8;
            int j = jt * 64 + jj;
            __half v8[8];
            if (j == 0) {
                #pragma unroll
                for (int i = 0; i < 8; i++) v8[i] = __float2half(null_k[h * 64 + d0 + i]);
            } else if (j < 257) {
                uint4 v = *(const uint4*)(Kh + ((size_t)(c * 256 + j - 1)) * INNER + h * 64 + d0);
                *(uint4*)v8 = v;
            } else {
                #pragma unroll
                for (int i = 0; i < 8; i++) v8[i] = __float2half(0.f);
            }
            #pragma unroll
            for (int i = 0; i < 8; i++) kvm[(d0 + i) * 72 + jj] = v8[i];
        }
        __syncthreads();

        float acc[2][4];
        #pragma unroll
        for (int nj = 0; nj < 2; nj++)
            #pragma unroll
            for (int q = 0; q < 4; q++) acc[nj][q] = 0.f;

        #pragma unroll
        for (int kk = 0; kk < 4; kk++) {
            unsigned a[4], b[4];
            ldsm_x4(a[0], a[1], a[2], a[3],
                    qb + (wm * 16 + lr) * 144 + (kk * 16 + lo) * 2);
            ldsm_x4t(b[0], b[1], b[2], b[3],
                     kb + (kk * 16 + lr) * 144 + (wn * 16 + lo) * 2);
            mma_f16(acc[0], a, b);
            mma_f16(acc[1], a, b + 2);
        }
        #pragma unroll
        for (int nj = 0; nj < 2; nj++) {
            int cs = jt * 64 + wn * 16 + nj * 8 + lk * 2;
            if (cs < 263) {
                S[(wm * 16 + lg) * 264 + cs]     = acc[nj][0];
                S[(wm * 16 + lg) * 264 + cs + 1] = acc[nj][1];
                S[(wm * 16 + lg + 8) * 264 + cs]     = acc[nj][2];
                S[(wm * 16 + lg + 8) * 264 + cs + 1] = acc[nj][3];
            }
        }
        __syncthreads();
    }

    // ---- softmax (257 cols), P fp16 with cols 257..327 zeroed ----
    for (int r = warp; r < 32; r += 8) {
        float v[9], mx = -1e30f;
        #pragma unroll
        for (int q = 0; q < 9; q++) {
            int j = lane + 32 * q;
            v[q] = (j < 257) ? S[r * 264 + j] : -1e30f;
            mx = fmaxf(mx, v[q]);
        }
        #pragma unroll
        for (int o = 16; o; o >>= 1) mx = fmaxf(mx, __shfl_xor_sync(~0u, mx, o));
        float sum = 0.f;
        #pragma unroll
        for (int q = 0; q < 9; q++) {
            int j = lane + 32 * q;
            v[q] = (j < 257) ? __expf(v[q] - mx) : 0.f;
            sum += v[q];
        }
        #pragma unroll
        for (int o = 16; o; o >>= 1) sum += __shfl_xor_sync(~0u, sum, o);
        float inv = 1.f / sum;
        #pragma unroll
        for (int q = 0; q < 9; q++) {
            int j = lane + 32 * q;
            if (j < 257) P[r * 328 + j] = __float2half(v[q] * inv);
        }
        #pragma unroll
        for (int q = 0; q < 3; q++) {
            int j = 257 + lane + 32 * q;
            if (j < 328) P[r * 328 + j] = __float2half(0.f);
        }
    }
    __syncthreads();

    // ---- O = P @ V over 5 kv tiles ----
    float oacc[2][4];
    #pragma unroll
    for (int nj = 0; nj < 2; nj++)
        #pragma unroll
        for (int q = 0; q < 4; q++) oacc[nj][q] = 0.f;

    for (int jt = 0; jt < 5; jt++) {
        for (int e = t; e < 512; e += 256) {
            int jj = e >> 3, c8 = (e & 7) * 8;
            int j = jt * 64 + jj;
            uint4 v;
            if (j == 0) {
                __half v8[8];
                #pragma unroll
                for (int i = 0; i < 8; i++) v8[i] = __float2half(null_v[h * 64 + c8 + i]);
                v = *(uint4*)v8;
            } else if (j < 257) {
                v = *(const uint4*)(Vh + ((size_t)(c * 256 + j - 1)) * INNER + h * 64 + c8);
            } else {
                v = make_uint4(0, 0, 0, 0);
            }
            *(uint4*)(kvm + jj * 72 + c8) = v;
        }
        __syncthreads();

        #pragma unroll
        for (int kk = 0; kk < 4; kk++) {
            unsigned a[4], b[4];
            ldsm_x4(a[0], a[1], a[2], a[3],
                    pb + (wm * 16 + lr) * 656 + (jt * 64 + kk * 16 + lo) * 2);
            ldsm_x4t(b[0], b[1], b[2], b[3],
                     kb + (kk * 16 + lr) * 144 + (wn * 16 + lo) * 2);
            mma_f16(oacc[0], a, b);
            mma_f16(oacc[1], a, b + 2);
        }
        __syncthreads();
    }

    #pragma unroll
    for (int nj = 0; nj < 2; nj++) {
        int col = h * 64 + wn * 16 + nj * 8 + lk * 2;
        __half2 p0 = __floats2half2_rn(oacc[nj][0], oacc[nj][1]);
        __half2 p1 = __floats2half2_rn(oacc[nj][2], oacc[nj][3]);
        *(unsigned*)(O + ((size_t)(c * 64 + r0 + wm * 16 + lg)) * INNER + col)     = *(unsigned*)&p0;
        *(unsigned*)(O + ((size_t)(c * 64 + r0 + wm * 16 + lg + 8)) * INNER + col) = *(unsigned*)&p1;
    }
}

// ---------------------------------------------------------------------------
// Zero the first 63 token rows of each batch
// ---------------------------------------------------------------------------
__global__ void zero_prefix_kernel(float* __restrict__ out)
{
    size_t idx = (size_t)blockIdx.x * 256 + threadIdx.x;
    const size_t total = (size_t)4 * 63 * 1024;
    if (idx < total) {
        size_t b   = idx / (63 * 1024);
        size_t rem = idx % (63 * 1024);
        out[b * (size_t)4096 * 1024 + rem] = 0.f;
    }
}

// ---------------------------------------------------------------------------
// Launch
// ---------------------------------------------------------------------------
extern "C" void kernel_launch(void* const* d_in, const int* in_sizes, int n_in,
                              void* d_out, int out_size)
{
    const float* x        = (const float*)d_in[0];
    const float* context  = (const float*)d_in[1];
    const float* q_pos    = (const float*)d_in[2];
    const float* k_pos    = (const float*)d_in[3];
    const float* Wq       = (const float*)d_in[4];
    const float* Wk       = (const float*)d_in[5];
    const float* Wv       = (const float*)d_in[6];
    const float* Wo       = (const float*)d_in[7];
    const float* bo       = (const float*)d_in[8];
    const float* null_k   = (const float*)d_in[9];
    const float* null_v   = (const float*)d_in[10];
    float* out            = (float*)d_out;

    __half *Qh, *Kh, *Vh, *Ob, *Xh, *Ch, *Wqh, *Wkh, *Wvh, *Woh;
    float *Kc, *Ks;
    cudaGetSymbolAddress((void**)&Qh,  g_Qh);
    cudaGetSymbolAddress((void**)&Kh,  g_Kh);
    cudaGetSymbolAddress((void**)&Vh,  g_Vh);
    cudaGetSymbolAddress((void**)&Ob,  g_O);
    cudaGetSymbolAddress((void**)&Xh,  g_xh);
    cudaGetSymbolAddress((void**)&Ch,  g_ch);
    cudaGetSymbolAddress((void**)&Wqh, g_wq);
    cudaGetSymbolAddress((void**)&Wkh, g_wk);
    cudaGetSymbolAddress((void**)&Wvh, g_wv);
    cudaGetSymbolAddress((void**)&Woh, g_wo);
    cudaGetSymbolAddress((void**)&Kc,  g_kcos);
    cudaGetSymbolAddress((void**)&Ks,  g_ksin);

    cudaFuncSetAttribute(f16_gemm<1,0,1>, cudaFuncAttributeMaxDynamicSharedMemorySize, FG_SMEM);
    cudaFuncSetAttribute(f16_gemm<0,0,1>, cudaFuncAttributeMaxDynamicSharedMemorySize, FG_SMEM);
    cudaFuncSetAttribute(f16_gemm<0,1,0>, cudaFuncAttributeMaxDynamicSharedMemorySize, FG_SMEM);
    cudaFuncSetAttribute(attn_kernel,     cudaFuncAttributeMaxDynamicSharedMemorySize, AT_SMEM);

    // conversions
    {
        int nw = (DIMM * INNER) / 4;
        cvt_f16_dual<<<(2*nw + 255) / 256, 256>>>(
            (const float4*)Wq, (uint2*)Wqh, nw, (const float4*)Wk, (uint2*)Wkh, nw);
        cvt_f16_dual<<<(2*nw + 255) / 256, 256>>>(
            (const float4*)Wv, (uint2*)Wvh, nw, (const float4*)Wo, (uint2*)Woh, nw);
        int nx4 = (NX * DIMM) / 4;
        int nc4 = (int)(((size_t)MKV * DIMM) / 4);
        cvt_f16_dual<<<(nx4 + nc4 + 255) / 256, 256>>>(
            (const float4*)x, (uint2*)Xh, nx4, (const float4*)context, (uint2*)Ch, nc4);
        rope_tab_kernel<<<32, 256>>>(k_pos, Kc, Ks);
    }

    // Q = shifted-x @ Wq * 0.125 (fp16 out), then rope row-0 per chunk
    {
        dim3 grid(INNER / 128, MQ / 128);
        f16_gemm<1, 0, 1><<<grid, 256, FG_SMEM>>>(Xh, Wqh, Qh, MQ, INNER, DIMM, nullptr, 0.125f);
        rope_q_kernel<<<256, 256>>>(Qh, q_pos + 63 * 64);
    }
    // K = context @ Wk (fp16), then rope all rows; V = context @ Wv (fp16)
    {
        dim3 grid(INNER / 128, MKV / 128);
        f16_gemm<0, 0, 1><<<grid, 256, FG_SMEM>>>(Ch, Wkh, Kh, MKV, INNER, DIMM, nullptr, 1.f);
        rope_k_kernel<<<65536, 256>>>(Kh, Kc, Ks);
        f16_gemm<0, 0, 1><<<grid, 256, FG_SMEM>>>(Ch, Wvh, Vh, MKV, INNER, DIMM, nullptr, 1.f);
    }
    // attention (tensor core)
    {
        dim3 grid(BK_CH, NH, 2);
        attn_kernel<<<grid, 256, AT_SMEM>>>(Qh, Kh, Vh, null_k, null_v, Ob);
    }
    // out = attn_out @ Wo + bo, scattered with +63 shift
    {
        dim3 grid(DIMM / 128, MQ / 128);
        f16_gemm<0, 1, 0><<<grid, 256, FG_SMEM>>>(Ob, Woh, out, MQ, DIMM, INNER, bo, 1.f);
    }
    // zero first 63 rows per batch
    {
        const int total = 4 * 63 * 1024;
        zero_prefix_kernel<<<(total + 255) / 256, 256>>>(out);
    }
}